// round 14
// baseline (speedup 1.0000x reference)
#include <cuda_runtime.h>
#include <cuda_bf16.h>
#include <cstdint>

#define Nn 50000
#define Ee 800000
#define NFd 16
#define Hd 128
#define OUTD 4
#define ET 64                           // edge tile
#define NT64 (Ee / ET)                  // 12500
#define MTILES ((Nn + 127) / 128)       // 391

// ---------------- scratch (device globals; no allocation) ----------------
__device__ __align__(16) float g_A[Nn * Hd];
__device__ __align__(16) float g_B[Nn * Hd];
__device__ __align__(16) float g_Hf[Nn * Hd];
__device__ __align__(16) float g_S[Nn * Hd];   // uint-encoded max buffer in layer0
__device__ int   g_deg[Nn];
__device__ int   g_rowptr[Nn + 1];
__device__ int   g_cursor[Nn];
__device__ int   g_colidx[Ee];
__device__ int   g_edst[Ee];
__device__ int   g_is64;
__device__ int   g_bsum[256];
__device__ __align__(16) unsigned short g_W2h_img[128 * 128];
__device__ __align__(16) unsigned short g_W2l_img[128 * 128];
__device__ __align__(16) unsigned short g_WabH[256 * 128];
__device__ __align__(16) unsigned short g_WabL[256 * 128];
__device__ __align__(16) unsigned short g_WsH[128 * 128];
__device__ __align__(16) unsigned short g_WsL[128 * 128];

__device__ __forceinline__ unsigned encf(float f) {
    unsigned u = __float_as_uint(f);
    return (u & 0x80000000u) ? ~u : (u | 0x80000000u);
}
__device__ __forceinline__ float decf(unsigned u) {
    return (u & 0x80000000u) ? __uint_as_float(u ^ 0x80000000u)
                             : __uint_as_float(~u);
}
__device__ __forceinline__ uint32_t smem_u32(const void* p) {
    uint32_t a;
    asm("{ .reg .u64 t; cvta.to.shared.u64 t, %1; cvt.u32.u64 %0, t; }"
        : "=r"(a) : "l"(p));
    return a;
}
#define LDMX4(r0, r1, r2, r3, a) \
    asm volatile("ldmatrix.sync.aligned.m8n8.x4.shared.b16 {%0,%1,%2,%3}, [%4];" \
                 : "=r"(r0), "=r"(r1), "=r"(r2), "=r"(r3) : "r"(a))
#define MMA16816(d0, d1, d2, d3, a0, a1, a2, a3, b0, b1) \
    asm volatile("mma.sync.aligned.m16n8k16.row.col.f32.bf16.bf16.f32 " \
                 "{%0,%1,%2,%3}, {%4,%5,%6,%7}, {%8,%9}, {%0,%1,%2,%3};" \
                 : "+f"(d0), "+f"(d1), "+f"(d2), "+f"(d3) \
                 : "r"(a0), "r"(a1), "r"(a2), "r"(a3), "r"(b0), "r"(b1))

// fast hi/lo bf16 split (packed cvt both ways)
__device__ __forceinline__ void splitbf(float x0, float x1, unsigned& hw, unsigned& lw) {
    unsigned hv;
    asm("cvt.rn.bf16x2.f32 %0, %1, %2;" : "=r"(hv) : "f"(x1), "f"(x0));
    float b0 = __uint_as_float(hv << 16);
    float b1 = __uint_as_float(hv & 0xffff0000u);
    float r0 = x0 - b0, r1 = x1 - b1;
    unsigned lv;
    asm("cvt.rn.bf16x2.f32 %0, %1, %2;" : "=r"(lv) : "f"(r1), "f"(r0));
    hw = hv; lw = lv;
}

// ---------------- build kernels ----------------
__global__ void k_zero_all(const void* ei) {
    int i = blockIdx.x * 256 + threadIdx.x;
    if (i == 0) {
        const long long* p = (const long long*)ei;
        int ok = 1;
        for (int j = 0; j < 128; j++) {
            long long v = p[j];
            if (v < 0 || v >= Nn) { ok = 0; break; }
        }
        g_is64 = ok;
    }
    if (i < Nn * Hd / 4) ((float4*)g_S)[i] = make_float4(0.f, 0.f, 0.f, 0.f);
    if (i < Nn) g_deg[i] = 0;
}
__global__ void k_deg(const void* ei) {
    int e = blockIdx.x * 256 + threadIdx.x;
    if (e >= Ee) return;
    int dst = g_is64 ? (int)((const long long*)ei)[Ee + e] : ((const int*)ei)[Ee + e];
    atomicAdd(&g_deg[dst], 1);
}
__global__ void k_scan1() {
    __shared__ int sh[256];
    int t = threadIdx.x, b = blockIdx.x;
    int i = b * 256 + t;
    int v = (i < Nn) ? g_deg[i] : 0;
    sh[t] = v;
    __syncthreads();
    for (int off = 1; off < 256; off <<= 1) {
        int u = (t >= off) ? sh[t - off] : 0;
        __syncthreads();
        sh[t] += u;
        __syncthreads();
    }
    if (i < Nn) g_rowptr[i + 1] = sh[t];
    if (t == 255) g_bsum[b] = sh[255];
}
__global__ void k_scan2(int nb) {
    __shared__ int sh[256];
    int t = threadIdx.x;
    sh[t] = (t < nb) ? g_bsum[t] : 0;
    __syncthreads();
    for (int off = 1; off < 256; off <<= 1) {
        int u = (t >= off) ? sh[t - off] : 0;
        __syncthreads();
        sh[t] += u;
        __syncthreads();
    }
    g_bsum[t] = (t > 0) ? sh[t - 1] : 0;
}
__global__ void k_scan3() {
    int t = threadIdx.x, b = blockIdx.x;
    int i = b * 256 + t;
    if (i < Nn) {
        int v = g_rowptr[i + 1] + g_bsum[b];
        g_rowptr[i + 1] = v;
        if (i + 1 < Nn) g_cursor[i + 1] = v;
    }
    if (i == 0) { g_rowptr[0] = 0; g_cursor[0] = 0; }
}
__global__ void k_scatter(const void* ei) {
    int e = blockIdx.x * 256 + threadIdx.x;
    if (e >= Ee) return;
    int src, dst;
    if (g_is64) {
        src = (int)((const long long*)ei)[e];
        dst = (int)((const long long*)ei)[Ee + e];
    } else {
        src = ((const int*)ei)[e];
        dst = ((const int*)ei)[Ee + e];
    }
    int pos = atomicAdd(&g_cursor[dst], 1);
    g_colidx[pos] = src;
    g_edst[pos] = dst;
}

// W2 (layer0) -> [n][k] rows of 256B, granule-XOR swizzle, bf16 hi/lo
__global__ void k_prepW2(const float* __restrict__ W2) {
    int idx = blockIdx.x * 256 + threadIdx.x;
    if (idx >= 128 * 128) return;
    int n = idx >> 7, k = idx & 127;
    float w = W2[k * 128 + n];
    __nv_bfloat16 h = __float2bfloat16_rn(w);
    __nv_bfloat16 l = __float2bfloat16_rn(w - __bfloat162float(h));
    int off = n * 256 + ((k * 2) ^ ((n & 7) << 4));
    g_W2h_img[off >> 1] = __bfloat16_as_ushort(h);
    g_W2l_img[off >> 1] = __bfloat16_as_ushort(l);
}
__global__ void k_prepNode(const float* __restrict__ W1,
                           const float* __restrict__ W2s) {
    int idx = blockIdx.x * 256 + threadIdx.x;
    if (idx >= 384 * 128) return;
    int np = idx >> 7, k = idx & 127;
    float w;
    if (np < 128)      w = W1[k * 128 + np] - W1[(k + 128) * 128 + np];
    else if (np < 256) w = W1[(k + 128) * 128 + (np - 128)];
    else               w = W2s[k * 128 + (np - 256)];
    __nv_bfloat16 h = __float2bfloat16_rn(w);
    __nv_bfloat16 l = __float2bfloat16_rn(w - __bfloat162float(h));
    if (np < 256) {
        int off = np * 256 + ((k * 2) ^ ((np & 7) << 4));
        g_WabH[off >> 1] = __bfloat16_as_ushort(h);
        g_WabL[off >> 1] = __bfloat16_as_ushort(l);
    } else {
        int n = np - 256;
        int off = n * 256 + ((k * 2) ^ ((n & 7) << 4));
        g_WsH[off >> 1] = __bfloat16_as_ushort(h);
        g_WsL[off >> 1] = __bfloat16_as_ushort(l);
    }
}

// ---------------- layer0 node GEMM (FIN=16, SIMT: tiny) ------------------
__global__ __launch_bounds__(128) void k_gemmAB16(const float* __restrict__ Hin,
                                                  const float* __restrict__ W1,
                                                  const float* __restrict__ b1) {
    __shared__ float sh[8][NFd];
    int c = threadIdx.x;
    int nb = blockIdx.x * 8;
    const float4* src4 = (const float4*)(Hin + (size_t)nb * NFd);
    for (int i = c; i < 8 * NFd / 4; i += 128) ((float4*)sh)[i] = src4[i];
    __syncthreads();
    float accA[8], accB[8];
#pragma unroll
    for (int m = 0; m < 8; m++) { accA[m] = 0.f; accB[m] = 0.f; }
    for (int k = 0; k < NFd; k += 4) {
        float wt0 = W1[(k + 0) * Hd + c], wt1 = W1[(k + 1) * Hd + c];
        float wt2 = W1[(k + 2) * Hd + c], wt3 = W1[(k + 3) * Hd + c];
        float wb0 = W1[(NFd + k + 0) * Hd + c], wb1 = W1[(NFd + k + 1) * Hd + c];
        float wb2 = W1[(NFd + k + 2) * Hd + c], wb3 = W1[(NFd + k + 3) * Hd + c];
        float d0 = wt0 - wb0, d1 = wt1 - wb1, d2 = wt2 - wb2, d3 = wt3 - wb3;
#pragma unroll
        for (int m = 0; m < 8; m++) {
            float4 h = *(const float4*)&sh[m][k];
            accA[m] += h.x * d0; accA[m] += h.y * d1;
            accA[m] += h.z * d2; accA[m] += h.w * d3;
            accB[m] += h.x * wb0; accB[m] += h.y * wb1;
            accB[m] += h.z * wb2; accB[m] += h.w * wb3;
        }
    }
    float bb = b1[c];
#pragma unroll
    for (int m = 0; m < 8; m++) {
        g_A[(size_t)(nb + m) * Hd + c] = accA[m] + bb;
        g_B[(size_t)(nb + m) * Hd + c] = accB[m];
    }
}

// ---------------- HMMA node GEMM: [g_A|g_B] = Hin @ [Wdiff|Wb] -----------
#define NAB_WH 0
#define NAB_WL 65536
#define NAB_PH 131072
#define NAB_PL 163840
#define NAB_TOT 196608

__global__ __launch_bounds__(512, 1) void k_gemmAB_h(const float* __restrict__ b1,
                                                     const float* __restrict__ bdec,
                                                     int fuse) {
    extern __shared__ char sm[];
    const uint32_t smb = smem_u32(sm);
    const int tid = threadIdx.x, wid = tid >> 5, lane = tid & 31;
    const int m0 = blockIdx.x * 128;

    {
        const uint4* wh = (const uint4*)g_WabH;
        const uint4* wl = (const uint4*)g_WabL;
        uint4* dh = (uint4*)(sm + NAB_WH);
        uint4* dl = (uint4*)(sm + NAB_WL);
        for (int i = tid; i < 4096; i += 512) { dh[i] = wh[i]; dl[i] = wl[i]; }
    }
#pragma unroll
    for (int i = 0; i < 4; i++) {
        int g = tid + i * 512;
        int e = g >> 4, q = g & 15;
        int row = m0 + e;
        float4 a0, a1;
        if (row < Nn) {
            if (fuse) {
                const uint4* Sr = (const uint4*)((const unsigned*)g_S + (size_t)row * 128) + q * 2;
                uint4 u0 = Sr[0], u1 = Sr[1];
                bool ok = g_deg[row] > 0;
                const float* bb = bdec + q * 8;
                a0.x = ok ? fmaxf(decf(u0.x) + bb[0], 0.f) : 0.f;
                a0.y = ok ? fmaxf(decf(u0.y) + bb[1], 0.f) : 0.f;
                a0.z = ok ? fmaxf(decf(u0.z) + bb[2], 0.f) : 0.f;
                a0.w = ok ? fmaxf(decf(u0.w) + bb[3], 0.f) : 0.f;
                a1.x = ok ? fmaxf(decf(u1.x) + bb[4], 0.f) : 0.f;
                a1.y = ok ? fmaxf(decf(u1.y) + bb[5], 0.f) : 0.f;
                a1.z = ok ? fmaxf(decf(u1.z) + bb[6], 0.f) : 0.f;
                a1.w = ok ? fmaxf(decf(u1.w) + bb[7], 0.f) : 0.f;
            } else {
                const float4* Hr = (const float4*)(g_Hf + (size_t)row * 128) + q * 2;
                a0 = Hr[0]; a1 = Hr[1];
            }
        } else {
            a0 = make_float4(0.f, 0.f, 0.f, 0.f);
            a1 = a0;
        }
        unsigned hw[4], lw[4];
        splitbf(a0.x, a0.y, hw[0], lw[0]);
        splitbf(a0.z, a0.w, hw[1], lw[1]);
        splitbf(a1.x, a1.y, hw[2], lw[2]);
        splitbf(a1.z, a1.w, hw[3], lw[3]);
        int off = e * 256 + ((q * 16) ^ ((e & 7) << 4));
        *(uint4*)(sm + NAB_PH + off) = make_uint4(hw[0], hw[1], hw[2], hw[3]);
        *(uint4*)(sm + NAB_PL + off) = make_uint4(lw[0], lw[1], lw[2], lw[3]);
    }
    __syncthreads();

    uint32_t ah[32], al[32];
    {
        int grp = lane >> 3;
        int row = 16 * (wid & 7) + (lane & 7) + (grp & 1) * 8;
        int kbb = (grp >> 1) * 16;
        int sw = (row & 7) << 4;
        uint32_t rowa = smb + NAB_PH + row * 256;
#pragma unroll
        for (int kk = 0; kk < 8; kk++) {
            uint32_t a = rowa + ((kbb + kk * 32) ^ sw);
            LDMX4(ah[kk * 4 + 0], ah[kk * 4 + 1], ah[kk * 4 + 2], ah[kk * 4 + 3], a);
            LDMX4(al[kk * 4 + 0], al[kk * 4 + 1], al[kk * 4 + 2], al[kk * 4 + 3],
                  a + (NAB_PL - NAB_PH));
        }
    }

    const int nh = wid >> 3;
    const int colbase = 128 * nh;
    const int e0 = 16 * (wid & 7) + (lane >> 2);
    const int gr0 = m0 + e0, gr1 = gr0 + 8;
    const int cl = 2 * (lane & 3);
    float* outArr = nh ? g_B : g_A;

    for (int tt = 0; tt < 16; tt++) {
        float d0 = 0.f, d1 = 0.f, d2 = 0.f, d3 = 0.f;
        int n = colbase + 8 * tt + (lane & 7);
        int nsw = (n & 7) << 4;
        uint32_t nbase = smb + NAB_WH + n * 256;
#pragma unroll
        for (int kk = 0; kk < 8; kk += 2) {
            uint32_t addr = nbase + ((kk * 32 + (lane >> 3) * 16) ^ nsw);
            uint32_t bh0, bh1, bh2, bh3, bl0, bl1, bl2, bl3;
            LDMX4(bh0, bh1, bh2, bh3, addr);
            LDMX4(bl0, bl1, bl2, bl3, addr + (NAB_WL - NAB_WH));
            const uint32_t* A0 = &ah[kk * 4];
            const uint32_t* A1 = &ah[kk * 4 + 4];
            const uint32_t* L0 = &al[kk * 4];
            const uint32_t* L1 = &al[kk * 4 + 4];
            MMA16816(d0, d1, d2, d3, A0[0], A0[1], A0[2], A0[3], bh0, bh1);
            MMA16816(d0, d1, d2, d3, A1[0], A1[1], A1[2], A1[3], bh2, bh3);
            MMA16816(d0, d1, d2, d3, A0[0], A0[1], A0[2], A0[3], bl0, bl1);
            MMA16816(d0, d1, d2, d3, A1[0], A1[1], A1[2], A1[3], bl2, bl3);
            MMA16816(d0, d1, d2, d3, L0[0], L0[1], L0[2], L0[3], bh0, bh1);
            MMA16816(d0, d1, d2, d3, L1[0], L1[1], L1[2], L1[3], bh2, bh3);
        }
        int c = 8 * tt + cl;
        float bb0 = 0.f, bb1 = 0.f;
        if (nh == 0) { bb0 = b1[c]; bb1 = b1[c + 1]; }
        if (gr0 < Nn)
            *(float2*)(outArr + (size_t)gr0 * 128 + c) = make_float2(d0 + bb0, d1 + bb1);
        if (gr1 < Nn)
            *(float2*)(outArr + (size_t)gr1 * 128 + c) = make_float2(d2 + bb0, d3 + bb1);
    }
}

// ---------------- HMMA node GEMM: g_Hf = f((g_S/deg)@W2 + b2) ------------
#define NS_WH 0
#define NS_WL 32768
#define NS_PH 65536
#define NS_PL 98304
#define NS_SINV 131072
#define NS_WF   131584
#define NS_TOT  (131584 + 2048)

__global__ __launch_bounds__(256, 1) void k_gemmS_h(const float* __restrict__ b2,
                                                    int doRelu, int doFc,
                                                    const float* __restrict__ Wf,
                                                    const float* __restrict__ bfv,
                                                    float* __restrict__ out) {
    extern __shared__ char sm[];
    const uint32_t smb = smem_u32(sm);
    const int tid = threadIdx.x, wid = tid >> 5, lane = tid & 31;
    const int m0 = blockIdx.x * 128;
    float* sinv = (float*)(sm + NS_SINV);
    float4* sWf = (float4*)(sm + NS_WF);

    {
        const uint4* wh = (const uint4*)g_WsH;
        const uint4* wl = (const uint4*)g_WsL;
        uint4* dh = (uint4*)(sm + NS_WH);
        uint4* dl = (uint4*)(sm + NS_WL);
        for (int i = tid; i < 2048; i += 256) { dh[i] = wh[i]; dl[i] = wl[i]; }
    }
    if (tid < 128) {
        int row = m0 + tid;
        int d = (row < Nn) ? g_deg[row] : 0;
        sinv[tid] = (d > 0) ? 1.0f / (float)d : 0.f;
        if (doFc) sWf[tid] = ((const float4*)Wf)[tid];
    }
    __syncthreads();

#pragma unroll
    for (int i = 0; i < 8; i++) {
        int g = tid + i * 256;
        int e = g >> 4, q = g & 15;
        int row = m0 + e;
        float s = sinv[e];
        float4 a0, a1;
        if (row < Nn) {
            const float4* Sr = (const float4*)(g_S + (size_t)row * 128) + q * 2;
            a0 = Sr[0]; a1 = Sr[1];
            a0.x *= s; a0.y *= s; a0.z *= s; a0.w *= s;
            a1.x *= s; a1.y *= s; a1.z *= s; a1.w *= s;
        } else {
            a0 = make_float4(0.f, 0.f, 0.f, 0.f);
            a1 = a0;
        }
        unsigned hw[4], lw[4];
        splitbf(a0.x, a0.y, hw[0], lw[0]);
        splitbf(a0.z, a0.w, hw[1], lw[1]);
        splitbf(a1.x, a1.y, hw[2], lw[2]);
        splitbf(a1.z, a1.w, hw[3], lw[3]);
        int off = e * 256 + ((q * 16) ^ ((e & 7) << 4));
        *(uint4*)(sm + NS_PH + off) = make_uint4(hw[0], hw[1], hw[2], hw[3]);
        *(uint4*)(sm + NS_PL + off) = make_uint4(lw[0], lw[1], lw[2], lw[3]);
    }
    __syncthreads();

    uint32_t ah[32], al[32];
    {
        int grp = lane >> 3;
        int row = 16 * wid + (lane & 7) + (grp & 1) * 8;
        int kbb = (grp >> 1) * 16;
        int sw = (row & 7) << 4;
        uint32_t rowa = smb + NS_PH + row * 256;
#pragma unroll
        for (int kk = 0; kk < 8; kk++) {
            uint32_t a = rowa + ((kbb + kk * 32) ^ sw);
            LDMX4(ah[kk * 4 + 0], ah[kk * 4 + 1], ah[kk * 4 + 2], ah[kk * 4 + 3], a);
            LDMX4(al[kk * 4 + 0], al[kk * 4 + 1], al[kk * 4 + 2], al[kk * 4 + 3],
                  a + (NS_PL - NS_PH));
        }
    }

    const int e0 = 16 * wid + (lane >> 2);
    const int gr0 = m0 + e0, gr1 = gr0 + 8;
    const int cl = 2 * (lane & 3);
    const bool z0 = sinv[e0] > 0.f, z1 = sinv[e0 + 8] > 0.f;

    float4 p0 = make_float4(0.f, 0.f, 0.f, 0.f);
    float4 p1 = make_float4(0.f, 0.f, 0.f, 0.f);

    for (int tt = 0; tt < 16; tt++) {
        float d0 = 0.f, d1 = 0.f, d2 = 0.f, d3 = 0.f;
        int n = 8 * tt + (lane & 7);
        int nsw = (n & 7) << 4;
        uint32_t nbase = smb + NS_WH + n * 256;
#pragma unroll
        for (int kk = 0; kk < 8; kk += 2) {
            uint32_t addr = nbase + ((kk * 32 + (lane >> 3) * 16) ^ nsw);
            uint32_t bh0, bh1, bh2, bh3, bl0, bl1, bl2, bl3;
            LDMX4(bh0, bh1, bh2, bh3, addr);
            LDMX4(bl0, bl1, bl2, bl3, addr + (NS_WL - NS_WH));
            const uint32_t* A0 = &ah[kk * 4];
            const uint32_t* A1 = &ah[kk * 4 + 4];
            const uint32_t* L0 = &al[kk * 4];
            const uint32_t* L1 = &al[kk * 4 + 4];
            MMA16816(d0, d1, d2, d3, A0[0], A0[1], A0[2], A0[3], bh0, bh1);
            MMA16816(d0, d1, d2, d3, A1[0], A1[1], A1[2], A1[3], bh2, bh3);
            MMA16816(d0, d1, d2, d3, A0[0], A0[1], A0[2], A0[3], bl0, bl1);
            MMA16816(d0, d1, d2, d3, A1[0], A1[1], A1[2], A1[3], bl2, bl3);
            MMA16816(d0, d1, d2, d3, L0[0], L0[1], L0[2], L0[3], bh0, bh1);
            MMA16816(d0, d1, d2, d3, L1[0], L1[1], L1[2], L1[3], bh2, bh3);
        }
        int c = 8 * tt + cl;
        float bb0 = b2[c], bb1 = b2[c + 1];
        float v0 = z0 ? (d0 + bb0) : 0.f;
        float v1 = z0 ? (d1 + bb1) : 0.f;
        float v2 = z1 ? (d2 + bb0) : 0.f;
        float v3 = z1 ? (d3 + bb1) : 0.f;
        if (doRelu) {
            v0 = fmaxf(v0, 0.f); v1 = fmaxf(v1, 0.f);
            v2 = fmaxf(v2, 0.f); v3 = fmaxf(v3, 0.f);
        }
        if (doFc) {
            float4 wc = sWf[c], wc1 = sWf[c + 1];
            p0.x += v0 * wc.x + v1 * wc1.x;
            p0.y += v0 * wc.y + v1 * wc1.y;
            p0.z += v0 * wc.z + v1 * wc1.z;
            p0.w += v0 * wc.w + v1 * wc1.w;
            p1.x += v2 * wc.x + v3 * wc1.x;
            p1.y += v2 * wc.y + v3 * wc1.y;
            p1.z += v2 * wc.z + v3 * wc1.z;
            p1.w += v2 * wc.w + v3 * wc1.w;
        } else {
            if (gr0 < Nn) *(float2*)(g_Hf + (size_t)gr0 * 128 + c) = make_float2(v0, v1);
            if (gr1 < Nn) *(float2*)(g_Hf + (size_t)gr1 * 128 + c) = make_float2(v2, v3);
        }
    }

    if (doFc) {
#pragma unroll
        for (int off = 1; off <= 2; off <<= 1) {
            p0.x += __shfl_xor_sync(0xffffffffu, p0.x, off);
            p0.y += __shfl_xor_sync(0xffffffffu, p0.y, off);
            p0.z += __shfl_xor_sync(0xffffffffu, p0.z, off);
            p0.w += __shfl_xor_sync(0xffffffffu, p0.w, off);
            p1.x += __shfl_xor_sync(0xffffffffu, p1.x, off);
            p1.y += __shfl_xor_sync(0xffffffffu, p1.y, off);
            p1.z += __shfl_xor_sync(0xffffffffu, p1.z, off);
            p1.w += __shfl_xor_sync(0xffffffffu, p1.w, off);
        }
        if ((lane & 3) == 0) {
            float4 bf4 = make_float4(bfv[0], bfv[1], bfv[2], bfv[3]);
            if (gr0 < Nn)
                ((float4*)out)[gr0] = make_float4(p0.x + bf4.x, p0.y + bf4.y,
                                                  p0.z + bf4.z, p0.w + bf4.w);
            if (gr1 < Nn)
                ((float4*)out)[gr1] = make_float4(p1.x + bf4.x, p1.y + bf4.y,
                                                  p1.z + bf4.z, p1.w + bf4.w);
        }
    }
}

// ---------------- layer0 edge GEMM (R13 + warp-local epilogue) -----------
#define DSTR 68
#define E_W2H 0
#define E_W2L 32768
#define E_P   65536
#define E_PL  (E_P + 16384)
#define E_TOT (E_P + 128 * DSTR * 4)    // 100352

__global__ __launch_bounds__(256, 2) void k_edge_hmma() {
    extern __shared__ char sm[];
    const uint32_t smb = smem_u32(sm);
    const int tid = threadIdx.x, wid = tid >> 5, lane = tid & 31;
    const int mslot = wid & 3;
    const int nh = wid >> 2;

    {
        const uint4* wh = (const uint4*)g_W2h_img;
        const uint4* wl = (const uint4*)g_W2l_img;
        uint4* dh = (uint4*)(sm + E_W2H);
        uint4* dl = (uint4*)(sm + E_W2L);
        for (int i = tid; i < 2048; i += 256) { dh[i] = wh[i]; dl[i] = wl[i]; }
    }
    __syncthreads();

    unsigned* encOut = (unsigned*)g_S;
    float* Dst = (float*)(sm + E_P);

    for (int t = blockIdx.x; t < NT64; t += gridDim.x) {
        const int ebase = t * ET;
#pragma unroll
        for (int i = 0; i < 4; i++) {
            int g = tid + i * 256;
            int e = g >> 4, q = g & 15;
            int dst = g_edst[ebase + e];
            int src = g_colidx[ebase + e];
            const float4* Ar = (const float4*)(g_A + (size_t)dst * 128) + q * 2;
            const float4* Br = (const float4*)(g_B + (size_t)src * 128) + q * 2;
            float4 a0 = Ar[0], a1 = Ar[1];
            float4 b0 = Br[0], b1 = Br[1];
            float v[8];
            v[0] = fmaxf(a0.x + b0.x, 0.f); v[1] = fmaxf(a0.y + b0.y, 0.f);
            v[2] = fmaxf(a0.z + b0.z, 0.f); v[3] = fmaxf(a0.w + b0.w, 0.f);
            v[4] = fmaxf(a1.x + b1.x, 0.f); v[5] = fmaxf(a1.y + b1.y, 0.f);
            v[6] = fmaxf(a1.z + b1.z, 0.f); v[7] = fmaxf(a1.w + b1.w, 0.f);
            unsigned hw[4], lw[4];
            splitbf(v[0], v[1], hw[0], lw[0]);
            splitbf(v[2], v[3], hw[1], lw[1]);
            splitbf(v[4], v[5], hw[2], lw[2]);
            splitbf(v[6], v[7], hw[3], lw[3]);
            int off = e * 256 + ((q * 16) ^ ((e & 7) << 4));
            *(uint4*)(sm + E_P + off) = make_uint4(hw[0], hw[1], hw[2], hw[3]);
            *(uint4*)(sm + E_PL + off) = make_uint4(lw[0], lw[1], lw[2], lw[3]);
        }
        __syncthreads();

        uint32_t ah[32], al[32];
        {
            int grp = lane >> 3;
            int row = 16 * mslot + (lane & 7) + (grp & 1) * 8;
            int kbb = (grp >> 1) * 16;
            int sw = (row & 7) << 4;
            uint32_t rowa = smb + E_P + row * 256;
#pragma unroll
            for (int kk = 0; kk < 8; kk++) {
                uint32_t a = rowa + ((kbb + kk * 32) ^ sw);
                LDMX4(ah[kk * 4 + 0], ah[kk * 4 + 1], ah[kk * 4 + 2], ah[kk * 4 + 3], a);
                LDMX4(al[kk * 4 + 0], al[kk * 4 + 1], al[kk * 4 + 2], al[kk * 4 + 3],
                      a + 16384);
            }
        }
        __syncthreads();

        // ---- MMA (writes this warp's Dst region: 16 edges x 64 cols) ----
        {
            const int e0 = 16 * mslot + (lane >> 2), e1 = e0 + 8;
            const int cl = 2 * (lane & 3);
#pragma unroll
            for (int tp = 0; tp < 4; tp++) {
                float da0 = 0.f, da1 = 0.f, da2 = 0.f, da3 = 0.f;
                float db0 = 0.f, db1 = 0.f, db2 = 0.f, db3 = 0.f;
                int na = nh * 64 + 16 * tp + (lane & 7);
                int nb = na + 8;
                int nswa = (na & 7) << 4, nswb = (nb & 7) << 4;
                uint32_t nbasea = smb + E_W2H + na * 256;
                uint32_t nbaseb = smb + E_W2H + nb * 256;
#pragma unroll
                for (int kk = 0; kk < 8; kk += 2) {
                    uint32_t ka = ((kk * 32 + (lane >> 3) * 16));
                    uint32_t addra = nbasea + (ka ^ nswa);
                    uint32_t addrb = nbaseb + (ka ^ nswb);
                    uint32_t ah0, ah1, ah2, ah3, al0, al1, al2, al3;
                    uint32_t bh0, bh1, bh2, bh3, bl0, bl1, bl2, bl3;
                    LDMX4(ah0, ah1, ah2, ah3, addra);
                    LDMX4(al0, al1, al2, al3, addra + 32768);
                    LDMX4(bh0, bh1, bh2, bh3, addrb);
                    LDMX4(bl0, bl1, bl2, bl3, addrb + 32768);
                    const uint32_t* A0 = &ah[kk * 4];
                    const uint32_t* A1 = &ah[kk * 4 + 4];
                    const uint32_t* L0 = &al[kk * 4];
                    const uint32_t* L1 = &al[kk * 4 + 4];
                    MMA16816(da0, da1, da2, da3, A0[0], A0[1], A0[2], A0[3], ah0, ah1);
                    MMA16816(db0, db1, db2, db3, A0[0], A0[1], A0[2], A0[3], bh0, bh1);
                    MMA16816(da0, da1, da2, da3, A1[0], A1[1], A1[2], A1[3], ah2, ah3);
                    MMA16816(db0, db1, db2, db3, A1[0], A1[1], A1[2], A1[3], bh2, bh3);
                    MMA16816(da0, da1, da2, da3, A0[0], A0[1], A0[2], A0[3], al0, al1);
                    MMA16816(db0, db1, db2, db3, A0[0], A0[1], A0[2], A0[3], bl0, bl1);
                    MMA16816(da0, da1, da2, da3, A1[0], A1[1], A1[2], A1[3], al2, al3);
                    MMA16816(db0, db1, db2, db3, A1[0], A1[1], A1[2], A1[3], bl2, bl3);
                    MMA16816(da0, da1, da2, da3, L0[0], L0[1], L0[2], L0[3], ah0, ah1);
                    MMA16816(db0, db1, db2, db3, L0[0], L0[1], L0[2], L0[3], bh0, bh1);
                    MMA16816(da0, da1, da2, da3, L1[0], L1[1], L1[2], L1[3], ah2, ah3);
                    MMA16816(db0, db1, db2, db3, L1[0], L1[1], L1[2], L1[3], bh2, bh3);
                }
                int ca = nh * 64 + 16 * tp + cl;
                int cb = ca + 8;
                Dst[ca * DSTR + e0] = da0;
                Dst[(ca + 1) * DSTR + e0] = da1;
                Dst[ca * DSTR + e1] = da2;
                Dst[(ca + 1) * DSTR + e1] = da3;
                Dst[cb * DSTR + e0] = db0;
                Dst[(cb + 1) * DSTR + e0] = db1;
                Dst[cb * DSTR + e1] = db2;
                Dst[(cb + 1) * DSTR + e1] = db3;
            }
        }

        // ---- warp-local epilogue (no cross-warp Dst dependency) ----
        {
            const int er = 16 * mslot + (lane & 15);
            const int half = lane >> 4;
            int dstv = g_edst[ebase + er];
            unsigned mm = __match_any_sync(0xffffffffu, dstv) &
                          (half ? 0xFFFF0000u : 0x0000FFFFu);
            bool leader = ((int)(__ffs(mm) - 1) == lane);
            unsigned* outp = encOut + (size_t)dstv * 128 + nh * 64 + half * 32;
            __syncwarp();   // own-warp Dst stores visible to all lanes
#pragma unroll 8
            for (int j = 0; j < 32; j++) {
                int cidx = (j + 4 * half) & 31;   // stagger halves: disjoint banks
                float v = Dst[(nh * 64 + half * 32 + cidx) * DSTR + er];
                unsigned red = __reduce_max_sync(mm, encf(v));
                if (leader) atomicMax(outp + cidx, red);
            }
        }
        __syncthreads();   // all warps done with Dst before next build
    }
}

// ---------------- mean layers: S_i = sum_e relu(A_i + B_src), MLP=4 ------
__global__ __launch_bounds__(256) void k_edge_sum() {
    int gw = (blockIdx.x * 256 + threadIdx.x) >> 5;
    int lane = threadIdx.x & 31;
    if (gw >= Nn) return;
    const float4 a = *(const float4*)&g_A[(size_t)gw * Hd + lane * 4];
    float4 acc = make_float4(0.f, 0.f, 0.f, 0.f);
    int p = g_rowptr[gw], p1 = g_rowptr[gw + 1];
    for (; p + 4 <= p1; p += 4) {
        int j0 = g_colidx[p], j1 = g_colidx[p + 1];
        int j2 = g_colidx[p + 2], j3 = g_colidx[p + 3];
        float4 b0 = *(const float4*)&g_B[(size_t)j0 * Hd + lane * 4];
        float4 b1 = *(const float4*)&g_B[(size_t)j1 * Hd + lane * 4];
        float4 b2 = *(const float4*)&g_B[(size_t)j2 * Hd + lane * 4];
        float4 b3 = *(const float4*)&g_B[(size_t)j3 * Hd + lane * 4];
        acc.x += fmaxf(a.x + b0.x, 0.f) + fmaxf(a.x + b1.x, 0.f)
               + fmaxf(a.x + b2.x, 0.f) + fmaxf(a.x + b3.x, 0.f);
        acc.y += fmaxf(a.y + b0.y, 0.f) + fmaxf(a.y + b1.y, 0.f)
               + fmaxf(a.y + b2.y, 0.f) + fmaxf(a.y + b3.y, 0.f);
        acc.z += fmaxf(a.z + b0.z, 0.f) + fmaxf(a.z + b1.z, 0.f)
               + fmaxf(a.z + b2.z, 0.f) + fmaxf(a.z + b3.z, 0.f);
        acc.w += fmaxf(a.w + b0.w, 0.f) + fmaxf(a.w + b1.w, 0.f)
               + fmaxf(a.w + b2.w, 0.f) + fmaxf(a.w + b3.w, 0.f);
    }
    for (; p < p1; p++) {
        int j = g_colidx[p];
        float4 b = *(const float4*)&g_B[(size_t)j * Hd + lane * 4];
        acc.x += fmaxf(a.x + b.x, 0.f);
        acc.y += fmaxf(a.y + b.y, 0.f);
        acc.z += fmaxf(a.z + b.z, 0.f);
        acc.w += fmaxf(a.w + b.w, 0.f);
    }
    *(float4*)&g_S[(size_t)gw * Hd + lane * 4] = acc;
}

// ---------------- launch ----------------
extern "C" void kernel_launch(void* const* d_in, const int* in_sizes, int n_in,
                              void* d_out, int out_size) {
    const float* x   = (const float*)d_in[0];
    const void*  ei  = (const void*)d_in[2];
    const float* W01 = (const float*)d_in[3];
    const float* b01 = (const float*)d_in[4];
    const float* W02 = (const float*)d_in[5];
    const float* b02 = (const float*)d_in[6];
    const float* W11 = (const float*)d_in[7];
    const float* b11 = (const float*)d_in[8];
    const float* W12 = (const float*)d_in[9];
    const float* b12 = (const float*)d_in[10];
    const float* W21 = (const float*)d_in[11];
    const float* b21 = (const float*)d_in[12];
    const float* W22 = (const float*)d_in[13];
    const float* b22 = (const float*)d_in[14];
    const float* Wf  = (const float*)d_in[15];
    const float* bf  = (const float*)d_in[16];
    float* out = (float*)d_out;

    cudaFuncSetAttribute(k_edge_hmma, cudaFuncAttributeMaxDynamicSharedMemorySize, E_TOT);
    cudaFuncSetAttribute(k_gemmAB_h, cudaFuncAttributeMaxDynamicSharedMemorySize, NAB_TOT);
    cudaFuncSetAttribute(k_gemmS_h, cudaFuncAttributeMaxDynamicSharedMemorySize, NS_TOT);

    const int NB = (Nn + 255) / 256;

    // CSR build + zeroing (detect merged into zero_all)
    k_zero_all<<<(Nn * Hd / 4 + 255) / 256, 256>>>(ei);
    k_deg<<<Ee / 256, 256>>>(ei);
    k_scan1<<<NB, 256>>>();
    k_scan2<<<1, 256>>>(NB);
    k_scan3<<<NB, 256>>>();
    k_scatter<<<Ee / 256, 256>>>(ei);

    // layer 0 (max) on HMMA
    k_prepW2<<<64, 256>>>(W02);
    k_gemmAB16<<<Nn / 8, 128>>>(x, W01, b01);
    k_edge_hmma<<<296, 256, E_TOT>>>();

    // layer 1 (mean) + relu — layer0 decode fused into gemmAB_h
    k_prepNode<<<192, 256>>>(W11, W12);
    k_gemmAB_h<<<MTILES, 512, NAB_TOT>>>(b11, b02, 1);
    k_edge_sum<<<Nn / 8, 256>>>();
    k_gemmS_h<<<MTILES, 256, NS_TOT>>>(b12, 1, 0, nullptr, nullptr, nullptr);

    // layer 2 (mean), no relu; final FC fused into gemmS_h
    k_prepNode<<<192, 256>>>(W21, W22);
    k_gemmAB_h<<<MTILES, 512, NAB_TOT>>>(b21, nullptr, 0);
    k_edge_sum<<<Nn / 8, 256>>>();
    k_gemmS_h<<<MTILES, 256, NS_TOT>>>(b22, 0, 1, Wf, bf, out);
}

// round 15
// speedup vs baseline: 1.1307x; 1.1307x over previous
#include <cuda_runtime.h>
#include <cuda_bf16.h>
#include <cstdint>

#define Nn 50000
#define Ee 800000
#define NFd 16
#define Hd 128
#define OUTD 4
#define ET 64                           // edge tile
#define NT64 (Ee / ET)                  // 12500
#define MTILES ((Nn + 127) / 128)       // 391

// ---------------- scratch (device globals; no allocation) ----------------
__device__ __align__(16) float g_A[Nn * Hd];
__device__ __align__(16) float g_B[Nn * Hd];
__device__ __align__(16) float g_Hf[Nn * Hd];
__device__ __align__(16) float g_S[Nn * Hd];   // uint-encoded max buffer in layer0
__device__ int   g_deg[Nn];
__device__ int   g_rowptr[Nn + 1];
__device__ int   g_cursor[Nn];
__device__ int   g_colidx[Ee];
__device__ int   g_edst[Ee];
__device__ int   g_is64;
__device__ int   g_bsum[256];
__device__ __align__(16) unsigned short g_W2h_img[128 * 128];
__device__ __align__(16) unsigned short g_W2l_img[128 * 128];
__device__ __align__(16) unsigned short g_WabH[256 * 128];
__device__ __align__(16) unsigned short g_WabL[256 * 128];
__device__ __align__(16) unsigned short g_WsH[128 * 128];
__device__ __align__(16) unsigned short g_WsL[128 * 128];

__device__ __forceinline__ unsigned encf(float f) {
    unsigned u = __float_as_uint(f);
    return (u & 0x80000000u) ? ~u : (u | 0x80000000u);
}
__device__ __forceinline__ float decf(unsigned u) {
    return (u & 0x80000000u) ? __uint_as_float(u ^ 0x80000000u)
                             : __uint_as_float(~u);
}
__device__ __forceinline__ uint32_t smem_u32(const void* p) {
    uint32_t a;
    asm("{ .reg .u64 t; cvta.to.shared.u64 t, %1; cvt.u32.u64 %0, t; }"
        : "=r"(a) : "l"(p));
    return a;
}
#define LDMX4(r0, r1, r2, r3, a) \
    asm volatile("ldmatrix.sync.aligned.m8n8.x4.shared.b16 {%0,%1,%2,%3}, [%4];" \
                 : "=r"(r0), "=r"(r1), "=r"(r2), "=r"(r3) : "r"(a))
#define MMA16816(d0, d1, d2, d3, a0, a1, a2, a3, b0, b1) \
    asm volatile("mma.sync.aligned.m16n8k16.row.col.f32.bf16.bf16.f32 " \
                 "{%0,%1,%2,%3}, {%4,%5,%6,%7}, {%8,%9}, {%0,%1,%2,%3};" \
                 : "+f"(d0), "+f"(d1), "+f"(d2), "+f"(d3) \
                 : "r"(a0), "r"(a1), "r"(a2), "r"(a3), "r"(b0), "r"(b1))

// fast hi/lo bf16 split (packed cvt both ways)
__device__ __forceinline__ void splitbf(float x0, float x1, unsigned& hw, unsigned& lw) {
    unsigned hv;
    asm("cvt.rn.bf16x2.f32 %0, %1, %2;" : "=r"(hv) : "f"(x1), "f"(x0));
    float b0 = __uint_as_float(hv << 16);
    float b1 = __uint_as_float(hv & 0xffff0000u);
    float r0 = x0 - b0, r1 = x1 - b1;
    unsigned lv;
    asm("cvt.rn.bf16x2.f32 %0, %1, %2;" : "=r"(lv) : "f"(r1), "f"(r0));
    hw = hv; lw = lv;
}

// ---------------- build kernels ----------------
__global__ void k_zero_all(const void* ei) {
    int i = blockIdx.x * 256 + threadIdx.x;
    if (i == 0) {
        const long long* p = (const long long*)ei;
        int ok = 1;
        for (int j = 0; j < 128; j++) {
            long long v = p[j];
            if (v < 0 || v >= Nn) { ok = 0; break; }
        }
        g_is64 = ok;
    }
    if (i < Nn * Hd / 4) ((float4*)g_S)[i] = make_float4(0.f, 0.f, 0.f, 0.f);
    if (i < Nn) g_deg[i] = 0;
}
__global__ void k_deg(const void* ei) {
    int e = blockIdx.x * 256 + threadIdx.x;
    if (e >= Ee) return;
    int dst = g_is64 ? (int)((const long long*)ei)[Ee + e] : ((const int*)ei)[Ee + e];
    atomicAdd(&g_deg[dst], 1);
}
__global__ void k_scan1() {
    __shared__ int sh[256];
    int t = threadIdx.x, b = blockIdx.x;
    int i = b * 256 + t;
    int v = (i < Nn) ? g_deg[i] : 0;
    sh[t] = v;
    __syncthreads();
    for (int off = 1; off < 256; off <<= 1) {
        int u = (t >= off) ? sh[t - off] : 0;
        __syncthreads();
        sh[t] += u;
        __syncthreads();
    }
    if (i < Nn) g_rowptr[i + 1] = sh[t];
    if (t == 255) g_bsum[b] = sh[255];
}
__global__ void k_scan2(int nb) {
    __shared__ int sh[256];
    int t = threadIdx.x;
    sh[t] = (t < nb) ? g_bsum[t] : 0;
    __syncthreads();
    for (int off = 1; off < 256; off <<= 1) {
        int u = (t >= off) ? sh[t - off] : 0;
        __syncthreads();
        sh[t] += u;
        __syncthreads();
    }
    g_bsum[t] = (t > 0) ? sh[t - 1] : 0;
}
__global__ void k_scan3() {
    int t = threadIdx.x, b = blockIdx.x;
    int i = b * 256 + t;
    if (i < Nn) {
        int v = g_rowptr[i + 1] + g_bsum[b];
        g_rowptr[i + 1] = v;
        if (i + 1 < Nn) g_cursor[i + 1] = v;
    }
    if (i == 0) { g_rowptr[0] = 0; g_cursor[0] = 0; }
}
__global__ void k_scatter(const void* ei) {
    int e = blockIdx.x * 256 + threadIdx.x;
    if (e >= Ee) return;
    int src, dst;
    if (g_is64) {
        src = (int)((const long long*)ei)[e];
        dst = (int)((const long long*)ei)[Ee + e];
    } else {
        src = ((const int*)ei)[e];
        dst = ((const int*)ei)[Ee + e];
    }
    int pos = atomicAdd(&g_cursor[dst], 1);
    g_colidx[pos] = src;
    g_edst[pos] = dst;
}

// W2 (layer0) -> [n][k] rows of 256B, granule-XOR swizzle, bf16 hi/lo
__global__ void k_prepW2(const float* __restrict__ W2) {
    int idx = blockIdx.x * 256 + threadIdx.x;
    if (idx >= 128 * 128) return;
    int n = idx >> 7, k = idx & 127;
    float w = W2[k * 128 + n];
    __nv_bfloat16 h = __float2bfloat16_rn(w);
    __nv_bfloat16 l = __float2bfloat16_rn(w - __bfloat162float(h));
    int off = n * 256 + ((k * 2) ^ ((n & 7) << 4));
    g_W2h_img[off >> 1] = __bfloat16_as_ushort(h);
    g_W2l_img[off >> 1] = __bfloat16_as_ushort(l);
}
__global__ void k_prepNode(const float* __restrict__ W1,
                           const float* __restrict__ W2s) {
    int idx = blockIdx.x * 256 + threadIdx.x;
    if (idx >= 384 * 128) return;
    int np = idx >> 7, k = idx & 127;
    float w;
    if (np < 128)      w = W1[k * 128 + np] - W1[(k + 128) * 128 + np];
    else if (np < 256) w = W1[(k + 128) * 128 + (np - 128)];
    else               w = W2s[k * 128 + (np - 256)];
    __nv_bfloat16 h = __float2bfloat16_rn(w);
    __nv_bfloat16 l = __float2bfloat16_rn(w - __bfloat162float(h));
    if (np < 256) {
        int off = np * 256 + ((k * 2) ^ ((np & 7) << 4));
        g_WabH[off >> 1] = __bfloat16_as_ushort(h);
        g_WabL[off >> 1] = __bfloat16_as_ushort(l);
    } else {
        int n = np - 256;
        int off = n * 256 + ((k * 2) ^ ((n & 7) << 4));
        g_WsH[off >> 1] = __bfloat16_as_ushort(h);
        g_WsL[off >> 1] = __bfloat16_as_ushort(l);
    }
}

// ---------------- layer0 node GEMM (FIN=16, SIMT: tiny) ------------------
__global__ __launch_bounds__(128) void k_gemmAB16(const float* __restrict__ Hin,
                                                  const float* __restrict__ W1,
                                                  const float* __restrict__ b1) {
    __shared__ float sh[8][NFd];
    int c = threadIdx.x;
    int nb = blockIdx.x * 8;
    const float4* src4 = (const float4*)(Hin + (size_t)nb * NFd);
    for (int i = c; i < 8 * NFd / 4; i += 128) ((float4*)sh)[i] = src4[i];
    __syncthreads();
    float accA[8], accB[8];
#pragma unroll
    for (int m = 0; m < 8; m++) { accA[m] = 0.f; accB[m] = 0.f; }
    for (int k = 0; k < NFd; k += 4) {
        float wt0 = W1[(k + 0) * Hd + c], wt1 = W1[(k + 1) * Hd + c];
        float wt2 = W1[(k + 2) * Hd + c], wt3 = W1[(k + 3) * Hd + c];
        float wb0 = W1[(NFd + k + 0) * Hd + c], wb1 = W1[(NFd + k + 1) * Hd + c];
        float wb2 = W1[(NFd + k + 2) * Hd + c], wb3 = W1[(NFd + k + 3) * Hd + c];
        float d0 = wt0 - wb0, d1 = wt1 - wb1, d2 = wt2 - wb2, d3 = wt3 - wb3;
#pragma unroll
        for (int m = 0; m < 8; m++) {
            float4 h = *(const float4*)&sh[m][k];
            accA[m] += h.x * d0; accA[m] += h.y * d1;
            accA[m] += h.z * d2; accA[m] += h.w * d3;
            accB[m] += h.x * wb0; accB[m] += h.y * wb1;
            accB[m] += h.z * wb2; accB[m] += h.w * wb3;
        }
    }
    float bb = b1[c];
#pragma unroll
    for (int m = 0; m < 8; m++) {
        g_A[(size_t)(nb + m) * Hd + c] = accA[m] + bb;
        g_B[(size_t)(nb + m) * Hd + c] = accB[m];
    }
}

// ---------------- HMMA node GEMM: [g_A|g_B] = Hin @ [Wdiff|Wb] -----------
#define NAB_WH 0
#define NAB_WL 65536
#define NAB_PH 131072
#define NAB_PL 163840
#define NAB_TOT 196608

__global__ __launch_bounds__(512, 1) void k_gemmAB_h(const float* __restrict__ b1,
                                                     const float* __restrict__ bdec,
                                                     int fuse) {
    extern __shared__ char sm[];
    const uint32_t smb = smem_u32(sm);
    const int tid = threadIdx.x, wid = tid >> 5, lane = tid & 31;
    const int m0 = blockIdx.x * 128;

    {
        const uint4* wh = (const uint4*)g_WabH;
        const uint4* wl = (const uint4*)g_WabL;
        uint4* dh = (uint4*)(sm + NAB_WH);
        uint4* dl = (uint4*)(sm + NAB_WL);
        for (int i = tid; i < 4096; i += 512) { dh[i] = wh[i]; dl[i] = wl[i]; }
    }
#pragma unroll
    for (int i = 0; i < 4; i++) {
        int g = tid + i * 512;
        int e = g >> 4, q = g & 15;
        int row = m0 + e;
        float4 a0, a1;
        if (row < Nn) {
            if (fuse) {
                const uint4* Sr = (const uint4*)((const unsigned*)g_S + (size_t)row * 128) + q * 2;
                uint4 u0 = Sr[0], u1 = Sr[1];
                bool ok = g_deg[row] > 0;
                const float* bb = bdec + q * 8;
                a0.x = ok ? fmaxf(decf(u0.x) + bb[0], 0.f) : 0.f;
                a0.y = ok ? fmaxf(decf(u0.y) + bb[1], 0.f) : 0.f;
                a0.z = ok ? fmaxf(decf(u0.z) + bb[2], 0.f) : 0.f;
                a0.w = ok ? fmaxf(decf(u0.w) + bb[3], 0.f) : 0.f;
                a1.x = ok ? fmaxf(decf(u1.x) + bb[4], 0.f) : 0.f;
                a1.y = ok ? fmaxf(decf(u1.y) + bb[5], 0.f) : 0.f;
                a1.z = ok ? fmaxf(decf(u1.z) + bb[6], 0.f) : 0.f;
                a1.w = ok ? fmaxf(decf(u1.w) + bb[7], 0.f) : 0.f;
            } else {
                const float4* Hr = (const float4*)(g_Hf + (size_t)row * 128) + q * 2;
                a0 = Hr[0]; a1 = Hr[1];
            }
        } else {
            a0 = make_float4(0.f, 0.f, 0.f, 0.f);
            a1 = a0;
        }
        unsigned hw[4], lw[4];
        splitbf(a0.x, a0.y, hw[0], lw[0]);
        splitbf(a0.z, a0.w, hw[1], lw[1]);
        splitbf(a1.x, a1.y, hw[2], lw[2]);
        splitbf(a1.z, a1.w, hw[3], lw[3]);
        int off = e * 256 + ((q * 16) ^ ((e & 7) << 4));
        *(uint4*)(sm + NAB_PH + off) = make_uint4(hw[0], hw[1], hw[2], hw[3]);
        *(uint4*)(sm + NAB_PL + off) = make_uint4(lw[0], lw[1], lw[2], lw[3]);
    }
    __syncthreads();

    uint32_t ah[32], al[32];
    {
        int grp = lane >> 3;
        int row = 16 * (wid & 7) + (lane & 7) + (grp & 1) * 8;
        int kbb = (grp >> 1) * 16;
        int sw = (row & 7) << 4;
        uint32_t rowa = smb + NAB_PH + row * 256;
#pragma unroll
        for (int kk = 0; kk < 8; kk++) {
            uint32_t a = rowa + ((kbb + kk * 32) ^ sw);
            LDMX4(ah[kk * 4 + 0], ah[kk * 4 + 1], ah[kk * 4 + 2], ah[kk * 4 + 3], a);
            LDMX4(al[kk * 4 + 0], al[kk * 4 + 1], al[kk * 4 + 2], al[kk * 4 + 3],
                  a + (NAB_PL - NAB_PH));
        }
    }

    const int nh = wid >> 3;
    const int colbase = 128 * nh;
    const int e0 = 16 * (wid & 7) + (lane >> 2);
    const int gr0 = m0 + e0, gr1 = gr0 + 8;
    const int cl = 2 * (lane & 3);
    float* outArr = nh ? g_B : g_A;

    for (int tt = 0; tt < 16; tt++) {
        float d0 = 0.f, d1 = 0.f, d2 = 0.f, d3 = 0.f;
        int n = colbase + 8 * tt + (lane & 7);
        int nsw = (n & 7) << 4;
        uint32_t nbase = smb + NAB_WH + n * 256;
#pragma unroll
        for (int kk = 0; kk < 8; kk += 2) {
            uint32_t addr = nbase + ((kk * 32 + (lane >> 3) * 16) ^ nsw);
            uint32_t bh0, bh1, bh2, bh3, bl0, bl1, bl2, bl3;
            LDMX4(bh0, bh1, bh2, bh3, addr);
            LDMX4(bl0, bl1, bl2, bl3, addr + (NAB_WL - NAB_WH));
            const uint32_t* A0 = &ah[kk * 4];
            const uint32_t* A1 = &ah[kk * 4 + 4];
            const uint32_t* L0 = &al[kk * 4];
            const uint32_t* L1 = &al[kk * 4 + 4];
            MMA16816(d0, d1, d2, d3, A0[0], A0[1], A0[2], A0[3], bh0, bh1);
            MMA16816(d0, d1, d2, d3, A1[0], A1[1], A1[2], A1[3], bh2, bh3);
            MMA16816(d0, d1, d2, d3, A0[0], A0[1], A0[2], A0[3], bl0, bl1);
            MMA16816(d0, d1, d2, d3, A1[0], A1[1], A1[2], A1[3], bl2, bl3);
            MMA16816(d0, d1, d2, d3, L0[0], L0[1], L0[2], L0[3], bh0, bh1);
            MMA16816(d0, d1, d2, d3, L1[0], L1[1], L1[2], L1[3], bh2, bh3);
        }
        int c = 8 * tt + cl;
        float bb0 = 0.f, bb1 = 0.f;
        if (nh == 0) { bb0 = b1[c]; bb1 = b1[c + 1]; }
        if (gr0 < Nn)
            *(float2*)(outArr + (size_t)gr0 * 128 + c) = make_float2(d0 + bb0, d1 + bb1);
        if (gr1 < Nn)
            *(float2*)(outArr + (size_t)gr1 * 128 + c) = make_float2(d2 + bb0, d3 + bb1);
    }
}

// ---------------- HMMA node GEMM: g_Hf = f((g_S/deg)@W2 + b2) ------------
#define NS_WH 0
#define NS_WL 32768
#define NS_PH 65536
#define NS_PL 98304
#define NS_SINV 131072
#define NS_WF   131584
#define NS_TOT  (131584 + 2048)

__global__ __launch_bounds__(256, 1) void k_gemmS_h(const float* __restrict__ b2,
                                                    int doRelu, int doFc,
                                                    const float* __restrict__ Wf,
                                                    const float* __restrict__ bfv,
                                                    float* __restrict__ out) {
    extern __shared__ char sm[];
    const uint32_t smb = smem_u32(sm);
    const int tid = threadIdx.x, wid = tid >> 5, lane = tid & 31;
    const int m0 = blockIdx.x * 128;
    float* sinv = (float*)(sm + NS_SINV);
    float4* sWf = (float4*)(sm + NS_WF);

    {
        const uint4* wh = (const uint4*)g_WsH;
        const uint4* wl = (const uint4*)g_WsL;
        uint4* dh = (uint4*)(sm + NS_WH);
        uint4* dl = (uint4*)(sm + NS_WL);
        for (int i = tid; i < 2048; i += 256) { dh[i] = wh[i]; dl[i] = wl[i]; }
    }
    if (tid < 128) {
        int row = m0 + tid;
        int d = (row < Nn) ? g_deg[row] : 0;
        sinv[tid] = (d > 0) ? 1.0f / (float)d : 0.f;
        if (doFc) sWf[tid] = ((const float4*)Wf)[tid];
    }
    __syncthreads();

#pragma unroll
    for (int i = 0; i < 8; i++) {
        int g = tid + i * 256;
        int e = g >> 4, q = g & 15;
        int row = m0 + e;
        float s = sinv[e];
        float4 a0, a1;
        if (row < Nn) {
            const float4* Sr = (const float4*)(g_S + (size_t)row * 128) + q * 2;
            a0 = Sr[0]; a1 = Sr[1];
            a0.x *= s; a0.y *= s; a0.z *= s; a0.w *= s;
            a1.x *= s; a1.y *= s; a1.z *= s; a1.w *= s;
        } else {
            a0 = make_float4(0.f, 0.f, 0.f, 0.f);
            a1 = a0;
        }
        unsigned hw[4], lw[4];
        splitbf(a0.x, a0.y, hw[0], lw[0]);
        splitbf(a0.z, a0.w, hw[1], lw[1]);
        splitbf(a1.x, a1.y, hw[2], lw[2]);
        splitbf(a1.z, a1.w, hw[3], lw[3]);
        int off = e * 256 + ((q * 16) ^ ((e & 7) << 4));
        *(uint4*)(sm + NS_PH + off) = make_uint4(hw[0], hw[1], hw[2], hw[3]);
        *(uint4*)(sm + NS_PL + off) = make_uint4(lw[0], lw[1], lw[2], lw[3]);
    }
    __syncthreads();

    uint32_t ah[32], al[32];
    {
        int grp = lane >> 3;
        int row = 16 * wid + (lane & 7) + (grp & 1) * 8;
        int kbb = (grp >> 1) * 16;
        int sw = (row & 7) << 4;
        uint32_t rowa = smb + NS_PH + row * 256;
#pragma unroll
        for (int kk = 0; kk < 8; kk++) {
            uint32_t a = rowa + ((kbb + kk * 32) ^ sw);
            LDMX4(ah[kk * 4 + 0], ah[kk * 4 + 1], ah[kk * 4 + 2], ah[kk * 4 + 3], a);
            LDMX4(al[kk * 4 + 0], al[kk * 4 + 1], al[kk * 4 + 2], al[kk * 4 + 3],
                  a + (NS_PL - NS_PH));
        }
    }

    const int e0 = 16 * wid + (lane >> 2);
    const int gr0 = m0 + e0, gr1 = gr0 + 8;
    const int cl = 2 * (lane & 3);
    const bool z0 = sinv[e0] > 0.f, z1 = sinv[e0 + 8] > 0.f;

    float4 p0 = make_float4(0.f, 0.f, 0.f, 0.f);
    float4 p1 = make_float4(0.f, 0.f, 0.f, 0.f);

    for (int tt = 0; tt < 16; tt++) {
        float d0 = 0.f, d1 = 0.f, d2 = 0.f, d3 = 0.f;
        int n = 8 * tt + (lane & 7);
        int nsw = (n & 7) << 4;
        uint32_t nbase = smb + NS_WH + n * 256;
#pragma unroll
        for (int kk = 0; kk < 8; kk += 2) {
            uint32_t addr = nbase + ((kk * 32 + (lane >> 3) * 16) ^ nsw);
            uint32_t bh0, bh1, bh2, bh3, bl0, bl1, bl2, bl3;
            LDMX4(bh0, bh1, bh2, bh3, addr);
            LDMX4(bl0, bl1, bl2, bl3, addr + (NS_WL - NS_WH));
            const uint32_t* A0 = &ah[kk * 4];
            const uint32_t* A1 = &ah[kk * 4 + 4];
            const uint32_t* L0 = &al[kk * 4];
            const uint32_t* L1 = &al[kk * 4 + 4];
            MMA16816(d0, d1, d2, d3, A0[0], A0[1], A0[2], A0[3], bh0, bh1);
            MMA16816(d0, d1, d2, d3, A1[0], A1[1], A1[2], A1[3], bh2, bh3);
            MMA16816(d0, d1, d2, d3, A0[0], A0[1], A0[2], A0[3], bl0, bl1);
            MMA16816(d0, d1, d2, d3, A1[0], A1[1], A1[2], A1[3], bl2, bl3);
            MMA16816(d0, d1, d2, d3, L0[0], L0[1], L0[2], L0[3], bh0, bh1);
            MMA16816(d0, d1, d2, d3, L1[0], L1[1], L1[2], L1[3], bh2, bh3);
        }
        int c = 8 * tt + cl;
        float bb0 = b2[c], bb1 = b2[c + 1];
        float v0 = z0 ? (d0 + bb0) : 0.f;
        float v1 = z0 ? (d1 + bb1) : 0.f;
        float v2 = z1 ? (d2 + bb0) : 0.f;
        float v3 = z1 ? (d3 + bb1) : 0.f;
        if (doRelu) {
            v0 = fmaxf(v0, 0.f); v1 = fmaxf(v1, 0.f);
            v2 = fmaxf(v2, 0.f); v3 = fmaxf(v3, 0.f);
        }
        if (doFc) {
            float4 wc = sWf[c], wc1 = sWf[c + 1];
            p0.x += v0 * wc.x + v1 * wc1.x;
            p0.y += v0 * wc.y + v1 * wc1.y;
            p0.z += v0 * wc.z + v1 * wc1.z;
            p0.w += v0 * wc.w + v1 * wc1.w;
            p1.x += v2 * wc.x + v3 * wc1.x;
            p1.y += v2 * wc.y + v3 * wc1.y;
            p1.z += v2 * wc.z + v3 * wc1.z;
            p1.w += v2 * wc.w + v3 * wc1.w;
        } else {
            if (gr0 < Nn) *(float2*)(g_Hf + (size_t)gr0 * 128 + c) = make_float2(v0, v1);
            if (gr1 < Nn) *(float2*)(g_Hf + (size_t)gr1 * 128 + c) = make_float2(v2, v3);
        }
    }

    if (doFc) {
#pragma unroll
        for (int off = 1; off <= 2; off <<= 1) {
            p0.x += __shfl_xor_sync(0xffffffffu, p0.x, off);
            p0.y += __shfl_xor_sync(0xffffffffu, p0.y, off);
            p0.z += __shfl_xor_sync(0xffffffffu, p0.z, off);
            p0.w += __shfl_xor_sync(0xffffffffu, p0.w, off);
            p1.x += __shfl_xor_sync(0xffffffffu, p1.x, off);
            p1.y += __shfl_xor_sync(0xffffffffu, p1.y, off);
            p1.z += __shfl_xor_sync(0xffffffffu, p1.z, off);
            p1.w += __shfl_xor_sync(0xffffffffu, p1.w, off);
        }
        if ((lane & 3) == 0) {
            float4 bf4 = make_float4(bfv[0], bfv[1], bfv[2], bfv[3]);
            if (gr0 < Nn)
                ((float4*)out)[gr0] = make_float4(p0.x + bf4.x, p0.y + bf4.y,
                                                  p0.z + bf4.z, p0.w + bf4.w);
            if (gr1 < Nn)
                ((float4*)out)[gr1] = make_float4(p1.x + bf4.x, p1.y + bf4.y,
                                                  p1.z + bf4.z, p1.w + bf4.w);
        }
    }
}

// ---------------- layer0 edge GEMM (R13 known-good) ----------------------
#define DSTR 68
#define E_W2H 0
#define E_W2L 32768
#define E_P   65536
#define E_PL  (E_P + 16384)
#define E_TOT (E_P + 128 * DSTR * 4)    // 100352

__global__ __launch_bounds__(256, 2) void k_edge_hmma() {
    extern __shared__ char sm[];
    const uint32_t smb = smem_u32(sm);
    const int tid = threadIdx.x, wid = tid >> 5, lane = tid & 31;
    const int mslot = wid & 3;
    const int nh = wid >> 2;

    {
        const uint4* wh = (const uint4*)g_W2h_img;
        const uint4* wl = (const uint4*)g_W2l_img;
        uint4* dh = (uint4*)(sm + E_W2H);
        uint4* dl = (uint4*)(sm + E_W2L);
        for (int i = tid; i < 2048; i += 256) { dh[i] = wh[i]; dl[i] = wl[i]; }
    }
    __syncthreads();

    unsigned* encOut = (unsigned*)g_S;
    float* Dst = (float*)(sm + E_P);

    for (int t = blockIdx.x; t < NT64; t += gridDim.x) {
        const int ebase = t * ET;
#pragma unroll
        for (int i = 0; i < 4; i++) {
            int g = tid + i * 256;
            int e = g >> 4, q = g & 15;
            int dst = g_edst[ebase + e];
            int src = g_colidx[ebase + e];
            const float4* Ar = (const float4*)(g_A + (size_t)dst * 128) + q * 2;
            const float4* Br = (const float4*)(g_B + (size_t)src * 128) + q * 2;
            float4 a0 = Ar[0], a1 = Ar[1];
            float4 b0 = Br[0], b1 = Br[1];
            float v[8];
            v[0] = fmaxf(a0.x + b0.x, 0.f); v[1] = fmaxf(a0.y + b0.y, 0.f);
            v[2] = fmaxf(a0.z + b0.z, 0.f); v[3] = fmaxf(a0.w + b0.w, 0.f);
            v[4] = fmaxf(a1.x + b1.x, 0.f); v[5] = fmaxf(a1.y + b1.y, 0.f);
            v[6] = fmaxf(a1.z + b1.z, 0.f); v[7] = fmaxf(a1.w + b1.w, 0.f);
            unsigned hw[4], lw[4];
            splitbf(v[0], v[1], hw[0], lw[0]);
            splitbf(v[2], v[3], hw[1], lw[1]);
            splitbf(v[4], v[5], hw[2], lw[2]);
            splitbf(v[6], v[7], hw[3], lw[3]);
            int off = e * 256 + ((q * 16) ^ ((e & 7) << 4));
            *(uint4*)(sm + E_P + off) = make_uint4(hw[0], hw[1], hw[2], hw[3]);
            *(uint4*)(sm + E_PL + off) = make_uint4(lw[0], lw[1], lw[2], lw[3]);
        }
        __syncthreads();

        uint32_t ah[32], al[32];
        {
            int grp = lane >> 3;
            int row = 16 * mslot + (lane & 7) + (grp & 1) * 8;
            int kbb = (grp >> 1) * 16;
            int sw = (row & 7) << 4;
            uint32_t rowa = smb + E_P + row * 256;
#pragma unroll
            for (int kk = 0; kk < 8; kk++) {
                uint32_t a = rowa + ((kbb + kk * 32) ^ sw);
                LDMX4(ah[kk * 4 + 0], ah[kk * 4 + 1], ah[kk * 4 + 2], ah[kk * 4 + 3], a);
                LDMX4(al[kk * 4 + 0], al[kk * 4 + 1], al[kk * 4 + 2], al[kk * 4 + 3],
                      a + 16384);
            }
        }
        __syncthreads();

        {
            const int e0 = 16 * mslot + (lane >> 2), e1 = e0 + 8;
            const int cl = 2 * (lane & 3);
#pragma unroll
            for (int tp = 0; tp < 4; tp++) {
                float da0 = 0.f, da1 = 0.f, da2 = 0.f, da3 = 0.f;
                float db0 = 0.f, db1 = 0.f, db2 = 0.f, db3 = 0.f;
                int na = nh * 64 + 16 * tp + (lane & 7);
                int nb = na + 8;
                int nswa = (na & 7) << 4, nswb = (nb & 7) << 4;
                uint32_t nbasea = smb + E_W2H + na * 256;
                uint32_t nbaseb = smb + E_W2H + nb * 256;
#pragma unroll
                for (int kk = 0; kk < 8; kk += 2) {
                    uint32_t ka = ((kk * 32 + (lane >> 3) * 16));
                    uint32_t addra = nbasea + (ka ^ nswa);
                    uint32_t addrb = nbaseb + (ka ^ nswb);
                    uint32_t ah0, ah1, ah2, ah3, al0, al1, al2, al3;
                    uint32_t bh0, bh1, bh2, bh3, bl0, bl1, bl2, bl3;
                    LDMX4(ah0, ah1, ah2, ah3, addra);
                    LDMX4(al0, al1, al2, al3, addra + 32768);
                    LDMX4(bh0, bh1, bh2, bh3, addrb);
                    LDMX4(bl0, bl1, bl2, bl3, addrb + 32768);
                    const uint32_t* A0 = &ah[kk * 4];
                    const uint32_t* A1 = &ah[kk * 4 + 4];
                    const uint32_t* L0 = &al[kk * 4];
                    const uint32_t* L1 = &al[kk * 4 + 4];
                    MMA16816(da0, da1, da2, da3, A0[0], A0[1], A0[2], A0[3], ah0, ah1);
                    MMA16816(db0, db1, db2, db3, A0[0], A0[1], A0[2], A0[3], bh0, bh1);
                    MMA16816(da0, da1, da2, da3, A1[0], A1[1], A1[2], A1[3], ah2, ah3);
                    MMA16816(db0, db1, db2, db3, A1[0], A1[1], A1[2], A1[3], bh2, bh3);
                    MMA16816(da0, da1, da2, da3, A0[0], A0[1], A0[2], A0[3], al0, al1);
                    MMA16816(db0, db1, db2, db3, A0[0], A0[1], A0[2], A0[3], bl0, bl1);
                    MMA16816(da0, da1, da2, da3, A1[0], A1[1], A1[2], A1[3], al2, al3);
                    MMA16816(db0, db1, db2, db3, A1[0], A1[1], A1[2], A1[3], bl2, bl3);
                    MMA16816(da0, da1, da2, da3, L0[0], L0[1], L0[2], L0[3], ah0, ah1);
                    MMA16816(db0, db1, db2, db3, L0[0], L0[1], L0[2], L0[3], bh0, bh1);
                    MMA16816(da0, da1, da2, da3, L1[0], L1[1], L1[2], L1[3], ah2, ah3);
                    MMA16816(db0, db1, db2, db3, L1[0], L1[1], L1[2], L1[3], bh2, bh3);
                }
                int ca = nh * 64 + 16 * tp + cl;
                int cb = ca + 8;
                Dst[ca * DSTR + e0] = da0;
                Dst[(ca + 1) * DSTR + e0] = da1;
                Dst[ca * DSTR + e1] = da2;
                Dst[(ca + 1) * DSTR + e1] = da3;
                Dst[cb * DSTR + e0] = db0;
                Dst[(cb + 1) * DSTR + e0] = db1;
                Dst[cb * DSTR + e1] = db2;
                Dst[(cb + 1) * DSTR + e1] = db3;
            }
        }
        __syncthreads();

        {
            int e = (wid & 1) * 32 + lane;
            int dstv = g_edst[ebase + e];
            unsigned mm = __match_any_sync(0xffffffffu, dstv);
            bool leader = ((int)(__ffs(mm) - 1) == lane);
            int cbase = (wid >> 1) * 32;
            unsigned* outp = encOut + (size_t)dstv * 128 + cbase;
#pragma unroll 8
            for (int c = 0; c < 32; c++) {
                float v = Dst[(cbase + c) * DSTR + e];
                unsigned red = __reduce_max_sync(mm, encf(v));
                if (leader) atomicMax(outp + c, red);
            }
        }
        __syncthreads();
    }
}

// ---------------- mean layers: S_i = sum_e relu(A_i + B_src), MLP=4 ------
__global__ __launch_bounds__(256) void k_edge_sum() {
    int gw = (blockIdx.x * 256 + threadIdx.x) >> 5;
    int lane = threadIdx.x & 31;
    if (gw >= Nn) return;
    const float4 a = *(const float4*)&g_A[(size_t)gw * Hd + lane * 4];
    float4 acc = make_float4(0.f, 0.f, 0.f, 0.f);
    int p = g_rowptr[gw], p1 = g_rowptr[gw + 1];
    for (; p + 4 <= p1; p += 4) {
        int j0 = g_colidx[p], j1 = g_colidx[p + 1];
        int j2 = g_colidx[p + 2], j3 = g_colidx[p + 3];
        float4 b0 = *(const float4*)&g_B[(size_t)j0 * Hd + lane * 4];
        float4 b1 = *(const float4*)&g_B[(size_t)j1 * Hd + lane * 4];
        float4 b2 = *(const float4*)&g_B[(size_t)j2 * Hd + lane * 4];
        float4 b3 = *(const float4*)&g_B[(size_t)j3 * Hd + lane * 4];
        acc.x += fmaxf(a.x + b0.x, 0.f) + fmaxf(a.x + b1.x, 0.f)
               + fmaxf(a.x + b2.x, 0.f) + fmaxf(a.x + b3.x, 0.f);
        acc.y += fmaxf(a.y + b0.y, 0.f) + fmaxf(a.y + b1.y, 0.f)
               + fmaxf(a.y + b2.y, 0.f) + fmaxf(a.y + b3.y, 0.f);
        acc.z += fmaxf(a.z + b0.z, 0.f) + fmaxf(a.z + b1.z, 0.f)
               + fmaxf(a.z + b2.z, 0.f) + fmaxf(a.z + b3.z, 0.f);
        acc.w += fmaxf(a.w + b0.w, 0.f) + fmaxf(a.w + b1.w, 0.f)
               + fmaxf(a.w + b2.w, 0.f) + fmaxf(a.w + b3.w, 0.f);
    }
    for (; p < p1; p++) {
        int j = g_colidx[p];
        float4 b = *(const float4*)&g_B[(size_t)j * Hd + lane * 4];
        acc.x += fmaxf(a.x + b.x, 0.f);
        acc.y += fmaxf(a.y + b.y, 0.f);
        acc.z += fmaxf(a.z + b.z, 0.f);
        acc.w += fmaxf(a.w + b.w, 0.f);
    }
    *(float4*)&g_S[(size_t)gw * Hd + lane * 4] = acc;
}

// ---------------- launch ----------------
extern "C" void kernel_launch(void* const* d_in, const int* in_sizes, int n_in,
                              void* d_out, int out_size) {
    const float* x   = (const float*)d_in[0];
    const void*  ei  = (const void*)d_in[2];
    const float* W01 = (const float*)d_in[3];
    const float* b01 = (const float*)d_in[4];
    const float* W02 = (const float*)d_in[5];
    const float* b02 = (const float*)d_in[6];
    const float* W11 = (const float*)d_in[7];
    const float* b11 = (const float*)d_in[8];
    const float* W12 = (const float*)d_in[9];
    const float* b12 = (const float*)d_in[10];
    const float* W21 = (const float*)d_in[11];
    const float* b21 = (const float*)d_in[12];
    const float* W22 = (const float*)d_in[13];
    const float* b22 = (const float*)d_in[14];
    const float* Wf  = (const float*)d_in[15];
    const float* bf  = (const float*)d_in[16];
    float* out = (float*)d_out;

    cudaFuncSetAttribute(k_edge_hmma, cudaFuncAttributeMaxDynamicSharedMemorySize, E_TOT);
    cudaFuncSetAttribute(k_gemmAB_h, cudaFuncAttributeMaxDynamicSharedMemorySize, NAB_TOT);
    cudaFuncSetAttribute(k_gemmS_h, cudaFuncAttributeMaxDynamicSharedMemorySize, NS_TOT);

    const int NB = (Nn + 255) / 256;

    // CSR build + zeroing (detect merged into zero_all)
    k_zero_all<<<(Nn * Hd / 4 + 255) / 256, 256>>>(ei);
    k_deg<<<Ee / 256, 256>>>(ei);
    k_scan1<<<NB, 256>>>();
    k_scan2<<<1, 256>>>(NB);
    k_scan3<<<NB, 256>>>();
    k_scatter<<<Ee / 256, 256>>>(ei);

    // layer 0 (max) on HMMA
    k_prepW2<<<64, 256>>>(W02);
    k_gemmAB16<<<Nn / 8, 128>>>(x, W01, b01);
    k_edge_hmma<<<296, 256, E_TOT>>>();

    // layer 1 (mean) + relu — layer0 decode fused into gemmAB_h
    k_prepNode<<<192, 256>>>(W11, W12);
    k_gemmAB_h<<<MTILES, 512, NAB_TOT>>>(b11, b02, 1);
    k_edge_sum<<<Nn / 8, 256>>>();
    k_gemmS_h<<<MTILES, 256, NS_TOT>>>(b12, 1, 0, nullptr, nullptr, nullptr);

    // layer 2 (mean), no relu; final FC fused into gemmS_h
    k_prepNode<<<192, 256>>>(W21, W22);
    k_gemmAB_h<<<MTILES, 512, NAB_TOT>>>(b21, nullptr, 0);
    k_edge_sum<<<Nn / 8, 256>>>();
    k_gemmS_h<<<MTILES, 256, NS_TOT>>>(b22, 0, 1, Wf, bf, out);
}

// round 16
// speedup vs baseline: 1.1432x; 1.0110x over previous
#include <cuda_runtime.h>
#include <cuda_bf16.h>
#include <cstdint>

#define Nn 50000
#define Ee 800000
#define NFd 16
#define Hd 128
#define OUTD 4
#define ET 64                           // edge tile
#define NT64 (Ee / ET)                  // 12500
#define MTILES ((Nn + 127) / 128)       // 391

// ---------------- scratch (device globals; no allocation) ----------------
__device__ __align__(16) float g_A[Nn * Hd];
__device__ __align__(16) float g_B[Nn * Hd];
__device__ __align__(16) float g_Hf[Nn * Hd];
__device__ __align__(16) float g_S[Nn * Hd];   // uint-encoded max buffer in layer0
__device__ int   g_deg[Nn];
__device__ int   g_rowptr[Nn + 1];
__device__ int   g_cursor[Nn];
__device__ int   g_colidx[Ee];
__device__ int   g_edst[Ee];
__device__ int   g_is64;
__device__ int   g_bsum[256];
__device__ __align__(16) unsigned short g_W2h_img[128 * 128];
__device__ __align__(16) unsigned short g_W2l_img[128 * 128];
__device__ __align__(16) unsigned short g_WabH[256 * 128];
__device__ __align__(16) unsigned short g_WabL[256 * 128];
__device__ __align__(16) unsigned short g_WsH[128 * 128];
__device__ __align__(16) unsigned short g_WsL[128 * 128];

__device__ __forceinline__ unsigned encf(float f) {
    unsigned u = __float_as_uint(f);
    return (u & 0x80000000u) ? ~u : (u | 0x80000000u);
}
__device__ __forceinline__ float decf(unsigned u) {
    return (u & 0x80000000u) ? __uint_as_float(u ^ 0x80000000u)
                             : __uint_as_float(~u);
}
__device__ __forceinline__ uint32_t smem_u32(const void* p) {
    uint32_t a;
    asm("{ .reg .u64 t; cvta.to.shared.u64 t, %1; cvt.u32.u64 %0, t; }"
        : "=r"(a) : "l"(p));
    return a;
}
#define LDMX4(r0, r1, r2, r3, a) \
    asm volatile("ldmatrix.sync.aligned.m8n8.x4.shared.b16 {%0,%1,%2,%3}, [%4];" \
                 : "=r"(r0), "=r"(r1), "=r"(r2), "=r"(r3) : "r"(a))
#define MMA16816(d0, d1, d2, d3, a0, a1, a2, a3, b0, b1) \
    asm volatile("mma.sync.aligned.m16n8k16.row.col.f32.bf16.bf16.f32 " \
                 "{%0,%1,%2,%3}, {%4,%5,%6,%7}, {%8,%9}, {%0,%1,%2,%3};" \
                 : "+f"(d0), "+f"(d1), "+f"(d2), "+f"(d3) \
                 : "r"(a0), "r"(a1), "r"(a2), "r"(a3), "r"(b0), "r"(b1))

// fast hi/lo bf16 split (packed cvt both ways)
__device__ __forceinline__ void splitbf(float x0, float x1, unsigned& hw, unsigned& lw) {
    unsigned hv;
    asm("cvt.rn.bf16x2.f32 %0, %1, %2;" : "=r"(hv) : "f"(x1), "f"(x0));
    float b0 = __uint_as_float(hv << 16);
    float b1 = __uint_as_float(hv & 0xffff0000u);
    float r0 = x0 - b0, r1 = x1 - b1;
    unsigned lv;
    asm("cvt.rn.bf16x2.f32 %0, %1, %2;" : "=r"(lv) : "f"(r1), "f"(r0));
    hw = hv; lw = lv;
}
__device__ __forceinline__ unsigned hibf(float x0, float x1) {
    unsigned hv;
    asm("cvt.rn.bf16x2.f32 %0, %1, %2;" : "=r"(hv) : "f"(x1), "f"(x0));
    return hv;
}

// ---------------- build kernels ----------------
__global__ void k_zero_all(const void* ei) {
    int i = blockIdx.x * 256 + threadIdx.x;
    if (i == 0) {
        const long long* p = (const long long*)ei;
        int ok = 1;
        for (int j = 0; j < 128; j++) {
            long long v = p[j];
            if (v < 0 || v >= Nn) { ok = 0; break; }
        }
        g_is64 = ok;
    }
    if (i < Nn * Hd / 4) ((float4*)g_S)[i] = make_float4(0.f, 0.f, 0.f, 0.f);
    if (i < Nn) g_deg[i] = 0;
}
__global__ void k_deg(const void* ei) {
    int e = blockIdx.x * 256 + threadIdx.x;
    if (e >= Ee) return;
    int dst = g_is64 ? (int)((const long long*)ei)[Ee + e] : ((const int*)ei)[Ee + e];
    atomicAdd(&g_deg[dst], 1);
}
__global__ void k_scan1() {
    __shared__ int sh[256];
    int t = threadIdx.x, b = blockIdx.x;
    int i = b * 256 + t;
    int v = (i < Nn) ? g_deg[i] : 0;
    sh[t] = v;
    __syncthreads();
    for (int off = 1; off < 256; off <<= 1) {
        int u = (t >= off) ? sh[t - off] : 0;
        __syncthreads();
        sh[t] += u;
        __syncthreads();
    }
    if (i < Nn) g_rowptr[i + 1] = sh[t];
    if (t == 255) g_bsum[b] = sh[255];
}
__global__ void k_scan2(int nb) {
    __shared__ int sh[256];
    int t = threadIdx.x;
    sh[t] = (t < nb) ? g_bsum[t] : 0;
    __syncthreads();
    for (int off = 1; off < 256; off <<= 1) {
        int u = (t >= off) ? sh[t - off] : 0;
        __syncthreads();
        sh[t] += u;
        __syncthreads();
    }
    g_bsum[t] = (t > 0) ? sh[t - 1] : 0;
}
__global__ void k_scan3() {
    int t = threadIdx.x, b = blockIdx.x;
    int i = b * 256 + t;
    if (i < Nn) {
        int v = g_rowptr[i + 1] + g_bsum[b];
        g_rowptr[i + 1] = v;
        if (i + 1 < Nn) g_cursor[i + 1] = v;
    }
    if (i == 0) { g_rowptr[0] = 0; g_cursor[0] = 0; }
}
__global__ void k_scatter(const void* ei) {
    int e = blockIdx.x * 256 + threadIdx.x;
    if (e >= Ee) return;
    int src, dst;
    if (g_is64) {
        src = (int)((const long long*)ei)[e];
        dst = (int)((const long long*)ei)[Ee + e];
    } else {
        src = ((const int*)ei)[e];
        dst = ((const int*)ei)[Ee + e];
    }
    int pos = atomicAdd(&g_cursor[dst], 1);
    g_colidx[pos] = src;
    g_edst[pos] = dst;
}

// W2 (layer0) -> [n][k] rows of 256B, granule-XOR swizzle, bf16 hi/lo
__global__ void k_prepW2(const float* __restrict__ W2) {
    int idx = blockIdx.x * 256 + threadIdx.x;
    if (idx >= 128 * 128) return;
    int n = idx >> 7, k = idx & 127;
    float w = W2[k * 128 + n];
    __nv_bfloat16 h = __float2bfloat16_rn(w);
    __nv_bfloat16 l = __float2bfloat16_rn(w - __bfloat162float(h));
    int off = n * 256 + ((k * 2) ^ ((n & 7) << 4));
    g_W2h_img[off >> 1] = __bfloat16_as_ushort(h);
    g_W2l_img[off >> 1] = __bfloat16_as_ushort(l);
}
__global__ void k_prepNode(const float* __restrict__ W1,
                           const float* __restrict__ W2s) {
    int idx = blockIdx.x * 256 + threadIdx.x;
    if (idx >= 384 * 128) return;
    int np = idx >> 7, k = idx & 127;
    float w;
    if (np < 128)      w = W1[k * 128 + np] - W1[(k + 128) * 128 + np];
    else if (np < 256) w = W1[(k + 128) * 128 + (np - 128)];
    else               w = W2s[k * 128 + (np - 256)];
    __nv_bfloat16 h = __float2bfloat16_rn(w);
    __nv_bfloat16 l = __float2bfloat16_rn(w - __bfloat162float(h));
    if (np < 256) {
        int off = np * 256 + ((k * 2) ^ ((np & 7) << 4));
        g_WabH[off >> 1] = __bfloat16_as_ushort(h);
        g_WabL[off >> 1] = __bfloat16_as_ushort(l);
    } else {
        int n = np - 256;
        int off = n * 256 + ((k * 2) ^ ((n & 7) << 4));
        g_WsH[off >> 1] = __bfloat16_as_ushort(h);
        g_WsL[off >> 1] = __bfloat16_as_ushort(l);
    }
}

// ---------------- layer0 node GEMM (FIN=16, SIMT: tiny) ------------------
__global__ __launch_bounds__(128) void k_gemmAB16(const float* __restrict__ Hin,
                                                  const float* __restrict__ W1,
                                                  const float* __restrict__ b1) {
    __shared__ float sh[8][NFd];
    int c = threadIdx.x;
    int nb = blockIdx.x * 8;
    const float4* src4 = (const float4*)(Hin + (size_t)nb * NFd);
    for (int i = c; i < 8 * NFd / 4; i += 128) ((float4*)sh)[i] = src4[i];
    __syncthreads();
    float accA[8], accB[8];
#pragma unroll
    for (int m = 0; m < 8; m++) { accA[m] = 0.f; accB[m] = 0.f; }
    for (int k = 0; k < NFd; k += 4) {
        float wt0 = W1[(k + 0) * Hd + c], wt1 = W1[(k + 1) * Hd + c];
        float wt2 = W1[(k + 2) * Hd + c], wt3 = W1[(k + 3) * Hd + c];
        float wb0 = W1[(NFd + k + 0) * Hd + c], wb1 = W1[(NFd + k + 1) * Hd + c];
        float wb2 = W1[(NFd + k + 2) * Hd + c], wb3 = W1[(NFd + k + 3) * Hd + c];
        float d0 = wt0 - wb0, d1 = wt1 - wb1, d2 = wt2 - wb2, d3 = wt3 - wb3;
#pragma unroll
        for (int m = 0; m < 8; m++) {
            float4 h = *(const float4*)&sh[m][k];
            accA[m] += h.x * d0; accA[m] += h.y * d1;
            accA[m] += h.z * d2; accA[m] += h.w * d3;
            accB[m] += h.x * wb0; accB[m] += h.y * wb1;
            accB[m] += h.z * wb2; accB[m] += h.w * wb3;
        }
    }
    float bb = b1[c];
#pragma unroll
    for (int m = 0; m < 8; m++) {
        g_A[(size_t)(nb + m) * Hd + c] = accA[m] + bb;
        g_B[(size_t)(nb + m) * Hd + c] = accB[m];
    }
}

// ---------------- HMMA node GEMM: [g_A|g_B] = Hin @ [Wdiff|Wb] -----------
#define NAB_WH 0
#define NAB_WL 65536
#define NAB_PH 131072
#define NAB_PL 163840
#define NAB_TOT 196608

__global__ __launch_bounds__(512, 1) void k_gemmAB_h(const float* __restrict__ b1,
                                                     const float* __restrict__ bdec,
                                                     int fuse) {
    extern __shared__ char sm[];
    const uint32_t smb = smem_u32(sm);
    const int tid = threadIdx.x, wid = tid >> 5, lane = tid & 31;
    const int m0 = blockIdx.x * 128;

    {
        const uint4* wh = (const uint4*)g_WabH;
        const uint4* wl = (const uint4*)g_WabL;
        uint4* dh = (uint4*)(sm + NAB_WH);
        uint4* dl = (uint4*)(sm + NAB_WL);
        for (int i = tid; i < 4096; i += 512) { dh[i] = wh[i]; dl[i] = wl[i]; }
    }
#pragma unroll
    for (int i = 0; i < 4; i++) {
        int g = tid + i * 512;
        int e = g >> 4, q = g & 15;
        int row = m0 + e;
        float4 a0, a1;
        if (row < Nn) {
            if (fuse) {
                const uint4* Sr = (const uint4*)((const unsigned*)g_S + (size_t)row * 128) + q * 2;
                uint4 u0 = Sr[0], u1 = Sr[1];
                bool ok = g_deg[row] > 0;
                const float* bb = bdec + q * 8;
                a0.x = ok ? fmaxf(decf(u0.x) + bb[0], 0.f) : 0.f;
                a0.y = ok ? fmaxf(decf(u0.y) + bb[1], 0.f) : 0.f;
                a0.z = ok ? fmaxf(decf(u0.z) + bb[2], 0.f) : 0.f;
                a0.w = ok ? fmaxf(decf(u0.w) + bb[3], 0.f) : 0.f;
                a1.x = ok ? fmaxf(decf(u1.x) + bb[4], 0.f) : 0.f;
                a1.y = ok ? fmaxf(decf(u1.y) + bb[5], 0.f) : 0.f;
                a1.z = ok ? fmaxf(decf(u1.z) + bb[6], 0.f) : 0.f;
                a1.w = ok ? fmaxf(decf(u1.w) + bb[7], 0.f) : 0.f;
            } else {
                const float4* Hr = (const float4*)(g_Hf + (size_t)row * 128) + q * 2;
                a0 = Hr[0]; a1 = Hr[1];
            }
        } else {
            a0 = make_float4(0.f, 0.f, 0.f, 0.f);
            a1 = a0;
        }
        unsigned hw[4], lw[4];
        splitbf(a0.x, a0.y, hw[0], lw[0]);
        splitbf(a0.z, a0.w, hw[1], lw[1]);
        splitbf(a1.x, a1.y, hw[2], lw[2]);
        splitbf(a1.z, a1.w, hw[3], lw[3]);
        int off = e * 256 + ((q * 16) ^ ((e & 7) << 4));
        *(uint4*)(sm + NAB_PH + off) = make_uint4(hw[0], hw[1], hw[2], hw[3]);
        *(uint4*)(sm + NAB_PL + off) = make_uint4(lw[0], lw[1], lw[2], lw[3]);
    }
    __syncthreads();

    uint32_t ah[32], al[32];
    {
        int grp = lane >> 3;
        int row = 16 * (wid & 7) + (lane & 7) + (grp & 1) * 8;
        int kbb = (grp >> 1) * 16;
        int sw = (row & 7) << 4;
        uint32_t rowa = smb + NAB_PH + row * 256;
#pragma unroll
        for (int kk = 0; kk < 8; kk++) {
            uint32_t a = rowa + ((kbb + kk * 32) ^ sw);
            LDMX4(ah[kk * 4 + 0], ah[kk * 4 + 1], ah[kk * 4 + 2], ah[kk * 4 + 3], a);
            LDMX4(al[kk * 4 + 0], al[kk * 4 + 1], al[kk * 4 + 2], al[kk * 4 + 3],
                  a + (NAB_PL - NAB_PH));
        }
    }

    const int nh = wid >> 3;
    const int colbase = 128 * nh;
    const int e0 = 16 * (wid & 7) + (lane >> 2);
    const int gr0 = m0 + e0, gr1 = gr0 + 8;
    const int cl = 2 * (lane & 3);
    float* outArr = nh ? g_B : g_A;

    for (int tt = 0; tt < 16; tt++) {
        float d0 = 0.f, d1 = 0.f, d2 = 0.f, d3 = 0.f;
        int n = colbase + 8 * tt + (lane & 7);
        int nsw = (n & 7) << 4;
        uint32_t nbase = smb + NAB_WH + n * 256;
#pragma unroll
        for (int kk = 0; kk < 8; kk += 2) {
            uint32_t addr = nbase + ((kk * 32 + (lane >> 3) * 16) ^ nsw);
            uint32_t bh0, bh1, bh2, bh3, bl0, bl1, bl2, bl3;
            LDMX4(bh0, bh1, bh2, bh3, addr);
            LDMX4(bl0, bl1, bl2, bl3, addr + (NAB_WL - NAB_WH));
            const uint32_t* A0 = &ah[kk * 4];
            const uint32_t* A1 = &ah[kk * 4 + 4];
            const uint32_t* L0 = &al[kk * 4];
            const uint32_t* L1 = &al[kk * 4 + 4];
            MMA16816(d0, d1, d2, d3, A0[0], A0[1], A0[2], A0[3], bh0, bh1);
            MMA16816(d0, d1, d2, d3, A1[0], A1[1], A1[2], A1[3], bh2, bh3);
            MMA16816(d0, d1, d2, d3, A0[0], A0[1], A0[2], A0[3], bl0, bl1);
            MMA16816(d0, d1, d2, d3, A1[0], A1[1], A1[2], A1[3], bl2, bl3);
            MMA16816(d0, d1, d2, d3, L0[0], L0[1], L0[2], L0[3], bh0, bh1);
            MMA16816(d0, d1, d2, d3, L1[0], L1[1], L1[2], L1[3], bh2, bh3);
        }
        int c = 8 * tt + cl;
        float bb0 = 0.f, bb1 = 0.f;
        if (nh == 0) { bb0 = b1[c]; bb1 = b1[c + 1]; }
        if (gr0 < Nn)
            *(float2*)(outArr + (size_t)gr0 * 128 + c) = make_float2(d0 + bb0, d1 + bb1);
        if (gr1 < Nn)
            *(float2*)(outArr + (size_t)gr1 * 128 + c) = make_float2(d2 + bb0, d3 + bb1);
    }
}

// ---------------- HMMA node GEMM: g_Hf = f((g_S/deg)@W2 + b2) ------------
// single-buffered P (hi then lo) -> 98.8KB SMEM -> 2 CTA/SM
#define NS_WH 0
#define NS_WL 32768
#define NS_P  65536
#define NS_SINV 98304
#define NS_WF   98816
#define NS_TOT  (98816 + 2048)

__global__ __launch_bounds__(256, 2) void k_gemmS_h(const float* __restrict__ b2,
                                                    int doRelu, int doFc,
                                                    const float* __restrict__ Wf,
                                                    const float* __restrict__ bfv,
                                                    float* __restrict__ out) {
    extern __shared__ char sm[];
    const uint32_t smb = smem_u32(sm);
    const int tid = threadIdx.x, wid = tid >> 5, lane = tid & 31;
    const int m0 = blockIdx.x * 128;
    float* sinv = (float*)(sm + NS_SINV);
    float4* sWf = (float4*)(sm + NS_WF);

    {
        const uint4* wh = (const uint4*)g_WsH;
        const uint4* wl = (const uint4*)g_WsL;
        uint4* dh = (uint4*)(sm + NS_WH);
        uint4* dl = (uint4*)(sm + NS_WL);
        for (int i = tid; i < 2048; i += 256) { dh[i] = wh[i]; dl[i] = wl[i]; }
    }
    if (tid < 128) {
        int row = m0 + tid;
        int d = (row < Nn) ? g_deg[row] : 0;
        sinv[tid] = (d > 0) ? 1.0f / (float)d : 0.f;
        if (doFc) sWf[tid] = ((const float4*)Wf)[tid];
    }
    __syncthreads();

    // ---- build pass A: P <- hi words ----
#pragma unroll
    for (int i = 0; i < 8; i++) {
        int g = tid + i * 256;
        int e = g >> 4, q = g & 15;
        int row = m0 + e;
        float s = sinv[e];
        float4 a0, a1;
        if (row < Nn) {
            const float4* Sr = (const float4*)(g_S + (size_t)row * 128) + q * 2;
            a0 = Sr[0]; a1 = Sr[1];
            a0.x *= s; a0.y *= s; a0.z *= s; a0.w *= s;
            a1.x *= s; a1.y *= s; a1.z *= s; a1.w *= s;
        } else {
            a0 = make_float4(0.f, 0.f, 0.f, 0.f);
            a1 = a0;
        }
        unsigned hw[4];
        hw[0] = hibf(a0.x, a0.y);
        hw[1] = hibf(a0.z, a0.w);
        hw[2] = hibf(a1.x, a1.y);
        hw[3] = hibf(a1.z, a1.w);
        int off = e * 256 + ((q * 16) ^ ((e & 7) << 4));
        *(uint4*)(sm + NS_P + off) = make_uint4(hw[0], hw[1], hw[2], hw[3]);
    }
    __syncthreads();

    uint32_t ah[32], al[32];
    const int grp = lane >> 3;
    const int arow = 16 * wid + (lane & 7) + (grp & 1) * 8;
    const int kbb = (grp >> 1) * 16;
    const int asw = (arow & 7) << 4;
    {
        uint32_t rowa = smb + NS_P + arow * 256;
#pragma unroll
        for (int kk = 0; kk < 8; kk++) {
            uint32_t a = rowa + ((kbb + kk * 32) ^ asw);
            LDMX4(ah[kk * 4 + 0], ah[kk * 4 + 1], ah[kk * 4 + 2], ah[kk * 4 + 3], a);
        }
    }
    __syncthreads();   // all warps done reading P-hi

    // ---- build pass B: P <- lo words (recompute split) ----
#pragma unroll
    for (int i = 0; i < 8; i++) {
        int g = tid + i * 256;
        int e = g >> 4, q = g & 15;
        int row = m0 + e;
        float s = sinv[e];
        float4 a0, a1;
        if (row < Nn) {
            const float4* Sr = (const float4*)(g_S + (size_t)row * 128) + q * 2;
            a0 = Sr[0]; a1 = Sr[1];
            a0.x *= s; a0.y *= s; a0.z *= s; a0.w *= s;
            a1.x *= s; a1.y *= s; a1.z *= s; a1.w *= s;
        } else {
            a0 = make_float4(0.f, 0.f, 0.f, 0.f);
            a1 = a0;
        }
        unsigned hw, lw[4];
        splitbf(a0.x, a0.y, hw, lw[0]);
        splitbf(a0.z, a0.w, hw, lw[1]);
        splitbf(a1.x, a1.y, hw, lw[2]);
        splitbf(a1.z, a1.w, hw, lw[3]);
        int off = e * 256 + ((q * 16) ^ ((e & 7) << 4));
        *(uint4*)(sm + NS_P + off) = make_uint4(lw[0], lw[1], lw[2], lw[3]);
    }
    __syncthreads();

    {
        uint32_t rowa = smb + NS_P + arow * 256;
#pragma unroll
        for (int kk = 0; kk < 8; kk++) {
            uint32_t a = rowa + ((kbb + kk * 32) ^ asw);
            LDMX4(al[kk * 4 + 0], al[kk * 4 + 1], al[kk * 4 + 2], al[kk * 4 + 3], a);
        }
    }

    const int e0 = 16 * wid + (lane >> 2);
    const int gr0 = m0 + e0, gr1 = gr0 + 8;
    const int cl = 2 * (lane & 3);
    const bool z0 = sinv[e0] > 0.f, z1 = sinv[e0 + 8] > 0.f;

    float4 p0 = make_float4(0.f, 0.f, 0.f, 0.f);
    float4 p1 = make_float4(0.f, 0.f, 0.f, 0.f);

    for (int tt = 0; tt < 16; tt++) {
        float d0 = 0.f, d1 = 0.f, d2 = 0.f, d3 = 0.f;
        int n = 8 * tt + (lane & 7);
        int nsw = (n & 7) << 4;
        uint32_t nbase = smb + NS_WH + n * 256;
#pragma unroll
        for (int kk = 0; kk < 8; kk += 2) {
            uint32_t addr = nbase + ((kk * 32 + (lane >> 3) * 16) ^ nsw);
            uint32_t bh0, bh1, bh2, bh3, bl0, bl1, bl2, bl3;
            LDMX4(bh0, bh1, bh2, bh3, addr);
            LDMX4(bl0, bl1, bl2, bl3, addr + (NS_WL - NS_WH));
            const uint32_t* A0 = &ah[kk * 4];
            const uint32_t* A1 = &ah[kk * 4 + 4];
            const uint32_t* L0 = &al[kk * 4];
            const uint32_t* L1 = &al[kk * 4 + 4];
            MMA16816(d0, d1, d2, d3, A0[0], A0[1], A0[2], A0[3], bh0, bh1);
            MMA16816(d0, d1, d2, d3, A1[0], A1[1], A1[2], A1[3], bh2, bh3);
            MMA16816(d0, d1, d2, d3, A0[0], A0[1], A0[2], A0[3], bl0, bl1);
            MMA16816(d0, d1, d2, d3, A1[0], A1[1], A1[2], A1[3], bl2, bl3);
            MMA16816(d0, d1, d2, d3, L0[0], L0[1], L0[2], L0[3], bh0, bh1);
            MMA16816(d0, d1, d2, d3, L1[0], L1[1], L1[2], L1[3], bh2, bh3);
        }
        int c = 8 * tt + cl;
        float bb0 = b2[c], bb1 = b2[c + 1];
        float v0 = z0 ? (d0 + bb0) : 0.f;
        float v1 = z0 ? (d1 + bb1) : 0.f;
        float v2 = z1 ? (d2 + bb0) : 0.f;
        float v3 = z1 ? (d3 + bb1) : 0.f;
        if (doRelu) {
            v0 = fmaxf(v0, 0.f); v1 = fmaxf(v1, 0.f);
            v2 = fmaxf(v2, 0.f); v3 = fmaxf(v3, 0.f);
        }
        if (doFc) {
            float4 wc = sWf[c], wc1 = sWf[c + 1];
            p0.x += v0 * wc.x + v1 * wc1.x;
            p0.y += v0 * wc.y + v1 * wc1.y;
            p0.z += v0 * wc.z + v1 * wc1.z;
            p0.w += v0 * wc.w + v1 * wc1.w;
            p1.x += v2 * wc.x + v3 * wc1.x;
            p1.y += v2 * wc.y + v3 * wc1.y;
            p1.z += v2 * wc.z + v3 * wc1.z;
            p1.w += v2 * wc.w + v3 * wc1.w;
        } else {
            if (gr0 < Nn) *(float2*)(g_Hf + (size_t)gr0 * 128 + c) = make_float2(v0, v1);
            if (gr1 < Nn) *(float2*)(g_Hf + (size_t)gr1 * 128 + c) = make_float2(v2, v3);
        }
    }

    if (doFc) {
#pragma unroll
        for (int off = 1; off <= 2; off <<= 1) {
            p0.x += __shfl_xor_sync(0xffffffffu, p0.x, off);
            p0.y += __shfl_xor_sync(0xffffffffu, p0.y, off);
            p0.z += __shfl_xor_sync(0xffffffffu, p0.z, off);
            p0.w += __shfl_xor_sync(0xffffffffu, p0.w, off);
            p1.x += __shfl_xor_sync(0xffffffffu, p1.x, off);
            p1.y += __shfl_xor_sync(0xffffffffu, p1.y, off);
            p1.z += __shfl_xor_sync(0xffffffffu, p1.z, off);
            p1.w += __shfl_xor_sync(0xffffffffu, p1.w, off);
        }
        if ((lane & 3) == 0) {
            float4 bf4 = make_float4(bfv[0], bfv[1], bfv[2], bfv[3]);
            if (gr0 < Nn)
                ((float4*)out)[gr0] = make_float4(p0.x + bf4.x, p0.y + bf4.y,
                                                  p0.z + bf4.z, p0.w + bf4.w);
            if (gr1 < Nn)
                ((float4*)out)[gr1] = make_float4(p1.x + bf4.x, p1.y + bf4.y,
                                                  p1.z + bf4.z, p1.w + bf4.w);
        }
    }
}

// ---------------- layer0 edge GEMM (R13 known-good) ----------------------
#define DSTR 68
#define E_W2H 0
#define E_W2L 32768
#define E_P   65536
#define E_PL  (E_P + 16384)
#define E_TOT (E_P + 128 * DSTR * 4)    // 100352

__global__ __launch_bounds__(256, 2) void k_edge_hmma() {
    extern __shared__ char sm[];
    const uint32_t smb = smem_u32(sm);
    const int tid = threadIdx.x, wid = tid >> 5, lane = tid & 31;
    const int mslot = wid & 3;
    const int nh = wid >> 2;

    {
        const uint4* wh = (const uint4*)g_W2h_img;
        const uint4* wl = (const uint4*)g_W2l_img;
        uint4* dh = (uint4*)(sm + E_W2H);
        uint4* dl = (uint4*)(sm + E_W2L);
        for (int i = tid; i < 2048; i += 256) { dh[i] = wh[i]; dl[i] = wl[i]; }
    }
    __syncthreads();

    unsigned* encOut = (unsigned*)g_S;
    float* Dst = (float*)(sm + E_P);

    for (int t = blockIdx.x; t < NT64; t += gridDim.x) {
        const int ebase = t * ET;
#pragma unroll
        for (int i = 0; i < 4; i++) {
            int g = tid + i * 256;
            int e = g >> 4, q = g & 15;
            int dst = g_edst[ebase + e];
            int src = g_colidx[ebase + e];
            const float4* Ar = (const float4*)(g_A + (size_t)dst * 128) + q * 2;
            const float4* Br = (const float4*)(g_B + (size_t)src * 128) + q * 2;
            float4 a0 = Ar[0], a1 = Ar[1];
            float4 b0 = Br[0], b1 = Br[1];
            float v[8];
            v[0] = fmaxf(a0.x + b0.x, 0.f); v[1] = fmaxf(a0.y + b0.y, 0.f);
            v[2] = fmaxf(a0.z + b0.z, 0.f); v[3] = fmaxf(a0.w + b0.w, 0.f);
            v[4] = fmaxf(a1.x + b1.x, 0.f); v[5] = fmaxf(a1.y + b1.y, 0.f);
            v[6] = fmaxf(a1.z + b1.z, 0.f); v[7] = fmaxf(a1.w + b1.w, 0.f);
            unsigned hw[4], lw[4];
            splitbf(v[0], v[1], hw[0], lw[0]);
            splitbf(v[2], v[3], hw[1], lw[1]);
            splitbf(v[4], v[5], hw[2], lw[2]);
            splitbf(v[6], v[7], hw[3], lw[3]);
            int off = e * 256 + ((q * 16) ^ ((e & 7) << 4));
            *(uint4*)(sm + E_P + off) = make_uint4(hw[0], hw[1], hw[2], hw[3]);
            *(uint4*)(sm + E_PL + off) = make_uint4(lw[0], lw[1], lw[2], lw[3]);
        }
        __syncthreads();

        uint32_t ah[32], al[32];
        {
            int grp = lane >> 3;
            int row = 16 * mslot + (lane & 7) + (grp & 1) * 8;
            int kbb = (grp >> 1) * 16;
            int sw = (row & 7) << 4;
            uint32_t rowa = smb + E_P + row * 256;
#pragma unroll
            for (int kk = 0; kk < 8; kk++) {
                uint32_t a = rowa + ((kbb + kk * 32) ^ sw);
                LDMX4(ah[kk * 4 + 0], ah[kk * 4 + 1], ah[kk * 4 + 2], ah[kk * 4 + 3], a);
                LDMX4(al[kk * 4 + 0], al[kk * 4 + 1], al[kk * 4 + 2], al[kk * 4 + 3],
                      a + 16384);
            }
        }
        __syncthreads();

        {
            const int e0 = 16 * mslot + (lane >> 2), e1 = e0 + 8;
            const int cl = 2 * (lane & 3);
#pragma unroll
            for (int tp = 0; tp < 4; tp++) {
                float da0 = 0.f, da1 = 0.f, da2 = 0.f, da3 = 0.f;
                float db0 = 0.f, db1 = 0.f, db2 = 0.f, db3 = 0.f;
                int na = nh * 64 + 16 * tp + (lane & 7);
                int nb = na + 8;
                int nswa = (na & 7) << 4, nswb = (nb & 7) << 4;
                uint32_t nbasea = smb + E_W2H + na * 256;
                uint32_t nbaseb = smb + E_W2H + nb * 256;
#pragma unroll
                for (int kk = 0; kk < 8; kk += 2) {
                    uint32_t ka = ((kk * 32 + (lane >> 3) * 16));
                    uint32_t addra = nbasea + (ka ^ nswa);
                    uint32_t addrb = nbaseb + (ka ^ nswb);
                    uint32_t ah0, ah1, ah2, ah3, al0, al1, al2, al3;
                    uint32_t bh0, bh1, bh2, bh3, bl0, bl1, bl2, bl3;
                    LDMX4(ah0, ah1, ah2, ah3, addra);
                    LDMX4(al0, al1, al2, al3, addra + 32768);
                    LDMX4(bh0, bh1, bh2, bh3, addrb);
                    LDMX4(bl0, bl1, bl2, bl3, addrb + 32768);
                    const uint32_t* A0 = &ah[kk * 4];
                    const uint32_t* A1 = &ah[kk * 4 + 4];
                    const uint32_t* L0 = &al[kk * 4];
                    const uint32_t* L1 = &al[kk * 4 + 4];
                    MMA16816(da0, da1, da2, da3, A0[0], A0[1], A0[2], A0[3], ah0, ah1);
                    MMA16816(db0, db1, db2, db3, A0[0], A0[1], A0[2], A0[3], bh0, bh1);
                    MMA16816(da0, da1, da2, da3, A1[0], A1[1], A1[2], A1[3], ah2, ah3);
                    MMA16816(db0, db1, db2, db3, A1[0], A1[1], A1[2], A1[3], bh2, bh3);
                    MMA16816(da0, da1, da2, da3, A0[0], A0[1], A0[2], A0[3], al0, al1);
                    MMA16816(db0, db1, db2, db3, A0[0], A0[1], A0[2], A0[3], bl0, bl1);
                    MMA16816(da0, da1, da2, da3, A1[0], A1[1], A1[2], A1[3], al2, al3);
                    MMA16816(db0, db1, db2, db3, A1[0], A1[1], A1[2], A1[3], bl2, bl3);
                    MMA16816(da0, da1, da2, da3, L0[0], L0[1], L0[2], L0[3], ah0, ah1);
                    MMA16816(db0, db1, db2, db3, L0[0], L0[1], L0[2], L0[3], bh0, bh1);
                    MMA16816(da0, da1, da2, da3, L1[0], L1[1], L1[2], L1[3], ah2, ah3);
                    MMA16816(db0, db1, db2, db3, L1[0], L1[1], L1[2], L1[3], bh2, bh3);
                }
                int ca = nh * 64 + 16 * tp + cl;
                int cb = ca + 8;
                Dst[ca * DSTR + e0] = da0;
                Dst[(ca + 1) * DSTR + e0] = da1;
                Dst[ca * DSTR + e1] = da2;
                Dst[(ca + 1) * DSTR + e1] = da3;
                Dst[cb * DSTR + e0] = db0;
                Dst[(cb + 1) * DSTR + e0] = db1;
                Dst[cb * DSTR + e1] = db2;
                Dst[(cb + 1) * DSTR + e1] = db3;
            }
        }
        __syncthreads();

        {
            int e = (wid & 1) * 32 + lane;
            int dstv = g_edst[ebase + e];
            unsigned mm = __match_any_sync(0xffffffffu, dstv);
            bool leader = ((int)(__ffs(mm) - 1) == lane);
            int cbase = (wid >> 1) * 32;
            unsigned* outp = encOut + (size_t)dstv * 128 + cbase;
#pragma unroll 8
            for (int c = 0; c < 32; c++) {
                float v = Dst[(cbase + c) * DSTR + e];
                unsigned red = __reduce_max_sync(mm, encf(v));
                if (leader) atomicMax(outp + c, red);
            }
        }
        __syncthreads();
    }
}

// ---------------- mean layers: S_i = sum_e relu(A_i + B_src), MLP=4 ------
__global__ __launch_bounds__(256) void k_edge_sum() {
    int gw = (blockIdx.x * 256 + threadIdx.x) >> 5;
    int lane = threadIdx.x & 31;
    if (gw >= Nn) return;
    const float4 a = *(const float4*)&g_A[(size_t)gw * Hd + lane * 4];
    float4 acc = make_float4(0.f, 0.f, 0.f, 0.f);
    int p = g_rowptr[gw], p1 = g_rowptr[gw + 1];
    for (; p + 4 <= p1; p += 4) {
        int j0 = g_colidx[p], j1 = g_colidx[p + 1];
        int j2 = g_colidx[p + 2], j3 = g_colidx[p + 3];
        float4 b0 = *(const float4*)&g_B[(size_t)j0 * Hd + lane * 4];
        float4 b1 = *(const float4*)&g_B[(size_t)j1 * Hd + lane * 4];
        float4 b2 = *(const float4*)&g_B[(size_t)j2 * Hd + lane * 4];
        float4 b3 = *(const float4*)&g_B[(size_t)j3 * Hd + lane * 4];
        acc.x += fmaxf(a.x + b0.x, 0.f) + fmaxf(a.x + b1.x, 0.f)
               + fmaxf(a.x + b2.x, 0.f) + fmaxf(a.x + b3.x, 0.f);
        acc.y += fmaxf(a.y + b0.y, 0.f) + fmaxf(a.y + b1.y, 0.f)
               + fmaxf(a.y + b2.y, 0.f) + fmaxf(a.y + b3.y, 0.f);
        acc.z += fmaxf(a.z + b0.z, 0.f) + fmaxf(a.z + b1.z, 0.f)
               + fmaxf(a.z + b2.z, 0.f) + fmaxf(a.z + b3.z, 0.f);
        acc.w += fmaxf(a.w + b0.w, 0.f) + fmaxf(a.w + b1.w, 0.f)
               + fmaxf(a.w + b2.w, 0.f) + fmaxf(a.w + b3.w, 0.f);
    }
    for (; p < p1; p++) {
        int j = g_colidx[p];
        float4 b = *(const float4*)&g_B[(size_t)j * Hd + lane * 4];
        acc.x += fmaxf(a.x + b.x, 0.f);
        acc.y += fmaxf(a.y + b.y, 0.f);
        acc.z += fmaxf(a.z + b.z, 0.f);
        acc.w += fmaxf(a.w + b.w, 0.f);
    }
    *(float4*)&g_S[(size_t)gw * Hd + lane * 4] = acc;
}

// ---------------- launch ----------------
extern "C" void kernel_launch(void* const* d_in, const int* in_sizes, int n_in,
                              void* d_out, int out_size) {
    const float* x   = (const float*)d_in[0];
    const void*  ei  = (const void*)d_in[2];
    const float* W01 = (const float*)d_in[3];
    const float* b01 = (const float*)d_in[4];
    const float* W02 = (const float*)d_in[5];
    const float* b02 = (const float*)d_in[6];
    const float* W11 = (const float*)d_in[7];
    const float* b11 = (const float*)d_in[8];
    const float* W12 = (const float*)d_in[9];
    const float* b12 = (const float*)d_in[10];
    const float* W21 = (const float*)d_in[11];
    const float* b21 = (const float*)d_in[12];
    const float* W22 = (const float*)d_in[13];
    const float* b22 = (const float*)d_in[14];
    const float* Wf  = (const float*)d_in[15];
    const float* bf  = (const float*)d_in[16];
    float* out = (float*)d_out;

    cudaFuncSetAttribute(k_edge_hmma, cudaFuncAttributeMaxDynamicSharedMemorySize, E_TOT);
    cudaFuncSetAttribute(k_gemmAB_h, cudaFuncAttributeMaxDynamicSharedMemorySize, NAB_TOT);
    cudaFuncSetAttribute(k_gemmS_h, cudaFuncAttributeMaxDynamicSharedMemorySize, NS_TOT);

    const int NB = (Nn + 255) / 256;

    // CSR build + zeroing
    k_zero_all<<<(Nn * Hd / 4 + 255) / 256, 256>>>(ei);
    k_deg<<<Ee / 256, 256>>>(ei);
    k_scan1<<<NB, 256>>>();
    k_scan2<<<1, 256>>>(NB);
    k_scan3<<<NB, 256>>>();
    k_scatter<<<Ee / 256, 256>>>(ei);

    // layer 0 (max) on HMMA
    k_prepW2<<<64, 256>>>(W02);
    k_gemmAB16<<<Nn / 8, 128>>>(x, W01, b01);
    k_edge_hmma<<<296, 256, E_TOT>>>();

    // layer 1 (mean) + relu — layer0 decode fused into gemmAB_h
    k_prepNode<<<192, 256>>>(W11, W12);
    k_gemmAB_h<<<MTILES, 512, NAB_TOT>>>(b11, b02, 1);
    k_edge_sum<<<Nn / 8, 256>>>();
    k_gemmS_h<<<MTILES, 256, NS_TOT>>>(b12, 1, 0, nullptr, nullptr, nullptr);

    // layer 2 (mean), no relu; final FC fused into gemmS_h
    k_prepNode<<<192, 256>>>(W21, W22);
    k_gemmAB_h<<<MTILES, 512, NAB_TOT>>>(b21, nullptr, 0);
    k_edge_sum<<<Nn / 8, 256>>>();
    k_gemmS_h<<<MTILES, 256, NS_TOT>>>(b22, 0, 1, Wf, bf, out);
}

// round 17
// speedup vs baseline: 1.1448x; 1.0014x over previous
#include <cuda_runtime.h>
#include <cuda_bf16.h>
#include <cstdint>

#define Nn 50000
#define Ee 800000
#define NFd 16
#define Hd 128
#define OUTD 4
#define ET 64                           // edge tile
#define NT64 (Ee / ET)                  // 12500
#define MTILES ((Nn + 127) / 128)       // 391

// ---------------- scratch (device globals; no allocation) ----------------
__device__ __align__(16) float g_A[Nn * Hd];
__device__ __align__(16) float g_B[Nn * Hd];
__device__ __align__(16) float g_Hf[Nn * Hd];
__device__ __align__(16) float g_S[Nn * Hd];   // uint-encoded max buffer in layer0
__device__ int   g_deg[Nn];
__device__ int   g_rowptr[Nn + 1];
__device__ int   g_cursor[Nn];
__device__ int   g_colidx[Ee];
__device__ int   g_edst[Ee];
__device__ int   g_is64;
__device__ int   g_bsum[256];
__device__ __align__(16) unsigned short g_W2h_img[128 * 128];
__device__ __align__(16) unsigned short g_W2l_img[128 * 128];
__device__ __align__(16) unsigned short g_WabH[256 * 128];
__device__ __align__(16) unsigned short g_WabL[256 * 128];
__device__ __align__(16) unsigned short g_WsH[128 * 128];
__device__ __align__(16) unsigned short g_WsL[128 * 128];

__device__ __forceinline__ unsigned encf(float f) {
    unsigned u = __float_as_uint(f);
    return (u & 0x80000000u) ? ~u : (u | 0x80000000u);
}
__device__ __forceinline__ float decf(unsigned u) {
    return (u & 0x80000000u) ? __uint_as_float(u ^ 0x80000000u)
                             : __uint_as_float(~u);
}
__device__ __forceinline__ uint32_t smem_u32(const void* p) {
    uint32_t a;
    asm("{ .reg .u64 t; cvta.to.shared.u64 t, %1; cvt.u32.u64 %0, t; }"
        : "=r"(a) : "l"(p));
    return a;
}
#define LDMX4(r0, r1, r2, r3, a) \
    asm volatile("ldmatrix.sync.aligned.m8n8.x4.shared.b16 {%0,%1,%2,%3}, [%4];" \
                 : "=r"(r0), "=r"(r1), "=r"(r2), "=r"(r3) : "r"(a))
#define MMA16816(d0, d1, d2, d3, a0, a1, a2, a3, b0, b1) \
    asm volatile("mma.sync.aligned.m16n8k16.row.col.f32.bf16.bf16.f32 " \
                 "{%0,%1,%2,%3}, {%4,%5,%6,%7}, {%8,%9}, {%0,%1,%2,%3};" \
                 : "+f"(d0), "+f"(d1), "+f"(d2), "+f"(d3) \
                 : "r"(a0), "r"(a1), "r"(a2), "r"(a3), "r"(b0), "r"(b1))

// fast hi/lo bf16 split (packed cvt both ways)
__device__ __forceinline__ void splitbf(float x0, float x1, unsigned& hw, unsigned& lw) {
    unsigned hv;
    asm("cvt.rn.bf16x2.f32 %0, %1, %2;" : "=r"(hv) : "f"(x1), "f"(x0));
    float b0 = __uint_as_float(hv << 16);
    float b1 = __uint_as_float(hv & 0xffff0000u);
    float r0 = x0 - b0, r1 = x1 - b1;
    unsigned lv;
    asm("cvt.rn.bf16x2.f32 %0, %1, %2;" : "=r"(lv) : "f"(r1), "f"(r0));
    hw = hv; lw = lv;
}
__device__ __forceinline__ unsigned hibf(float x0, float x1) {
    unsigned hv;
    asm("cvt.rn.bf16x2.f32 %0, %1, %2;" : "=r"(hv) : "f"(x1), "f"(x0));
    return hv;
}

// ---------------- build kernels ----------------
__global__ void k_zero_all(const void* ei) {
    int i = blockIdx.x * 256 + threadIdx.x;
    if (i == 0) {
        const long long* p = (const long long*)ei;
        int ok = 1;
        for (int j = 0; j < 128; j++) {
            long long v = p[j];
            if (v < 0 || v >= Nn) { ok = 0; break; }
        }
        g_is64 = ok;
    }
    if (i < Nn * Hd / 4) ((float4*)g_S)[i] = make_float4(0.f, 0.f, 0.f, 0.f);
    if (i < Nn) g_deg[i] = 0;
}
__global__ void k_deg(const void* ei) {
    int e = blockIdx.x * 256 + threadIdx.x;
    if (e >= Ee) return;
    int dst = g_is64 ? (int)((const long long*)ei)[Ee + e] : ((const int*)ei)[Ee + e];
    atomicAdd(&g_deg[dst], 1);
}
__global__ void k_scan1() {
    __shared__ int sh[256];
    int t = threadIdx.x, b = blockIdx.x;
    int i = b * 256 + t;
    int v = (i < Nn) ? g_deg[i] : 0;
    sh[t] = v;
    __syncthreads();
    for (int off = 1; off < 256; off <<= 1) {
        int u = (t >= off) ? sh[t - off] : 0;
        __syncthreads();
        sh[t] += u;
        __syncthreads();
    }
    if (i < Nn) g_rowptr[i + 1] = sh[t];
    if (t == 255) g_bsum[b] = sh[255];
}
__global__ void k_scan2(int nb) {
    __shared__ int sh[256];
    int t = threadIdx.x;
    sh[t] = (t < nb) ? g_bsum[t] : 0;
    __syncthreads();
    for (int off = 1; off < 256; off <<= 1) {
        int u = (t >= off) ? sh[t - off] : 0;
        __syncthreads();
        sh[t] += u;
        __syncthreads();
    }
    g_bsum[t] = (t > 0) ? sh[t - 1] : 0;
}
__global__ void k_scan3() {
    int t = threadIdx.x, b = blockIdx.x;
    int i = b * 256 + t;
    if (i < Nn) {
        int v = g_rowptr[i + 1] + g_bsum[b];
        g_rowptr[i + 1] = v;
        if (i + 1 < Nn) g_cursor[i + 1] = v;
    }
    if (i == 0) { g_rowptr[0] = 0; g_cursor[0] = 0; }
}
__global__ void k_scatter(const void* ei) {
    int e = blockIdx.x * 256 + threadIdx.x;
    if (e >= Ee) return;
    int src, dst;
    if (g_is64) {
        src = (int)((const long long*)ei)[e];
        dst = (int)((const long long*)ei)[Ee + e];
    } else {
        src = ((const int*)ei)[e];
        dst = ((const int*)ei)[Ee + e];
    }
    int pos = atomicAdd(&g_cursor[dst], 1);
    g_colidx[pos] = src;
    g_edst[pos] = dst;
}

// W2 (layer0) -> [n][k] rows of 256B, granule-XOR swizzle, bf16 hi/lo
__global__ void k_prepW2(const float* __restrict__ W2) {
    int idx = blockIdx.x * 256 + threadIdx.x;
    if (idx >= 128 * 128) return;
    int n = idx >> 7, k = idx & 127;
    float w = W2[k * 128 + n];
    __nv_bfloat16 h = __float2bfloat16_rn(w);
    __nv_bfloat16 l = __float2bfloat16_rn(w - __bfloat162float(h));
    int off = n * 256 + ((k * 2) ^ ((n & 7) << 4));
    g_W2h_img[off >> 1] = __bfloat16_as_ushort(h);
    g_W2l_img[off >> 1] = __bfloat16_as_ushort(l);
}
__global__ void k_prepNode(const float* __restrict__ W1,
                           const float* __restrict__ W2s) {
    int idx = blockIdx.x * 256 + threadIdx.x;
    if (idx >= 384 * 128) return;
    int np = idx >> 7, k = idx & 127;
    float w;
    if (np < 128)      w = W1[k * 128 + np] - W1[(k + 128) * 128 + np];
    else if (np < 256) w = W1[(k + 128) * 128 + (np - 128)];
    else               w = W2s[k * 128 + (np - 256)];
    __nv_bfloat16 h = __float2bfloat16_rn(w);
    __nv_bfloat16 l = __float2bfloat16_rn(w - __bfloat162float(h));
    if (np < 256) {
        int off = np * 256 + ((k * 2) ^ ((np & 7) << 4));
        g_WabH[off >> 1] = __bfloat16_as_ushort(h);
        g_WabL[off >> 1] = __bfloat16_as_ushort(l);
    } else {
        int n = np - 256;
        int off = n * 256 + ((k * 2) ^ ((n & 7) << 4));
        g_WsH[off >> 1] = __bfloat16_as_ushort(h);
        g_WsL[off >> 1] = __bfloat16_as_ushort(l);
    }
}

// ---------------- layer0 node GEMM (FIN=16, SIMT: tiny) ------------------
__global__ __launch_bounds__(128) void k_gemmAB16(const float* __restrict__ Hin,
                                                  const float* __restrict__ W1,
                                                  const float* __restrict__ b1) {
    __shared__ float sh[8][NFd];
    int c = threadIdx.x;
    int nb = blockIdx.x * 8;
    const float4* src4 = (const float4*)(Hin + (size_t)nb * NFd);
    for (int i = c; i < 8 * NFd / 4; i += 128) ((float4*)sh)[i] = src4[i];
    __syncthreads();
    float accA[8], accB[8];
#pragma unroll
    for (int m = 0; m < 8; m++) { accA[m] = 0.f; accB[m] = 0.f; }
    for (int k = 0; k < NFd; k += 4) {
        float wt0 = W1[(k + 0) * Hd + c], wt1 = W1[(k + 1) * Hd + c];
        float wt2 = W1[(k + 2) * Hd + c], wt3 = W1[(k + 3) * Hd + c];
        float wb0 = W1[(NFd + k + 0) * Hd + c], wb1 = W1[(NFd + k + 1) * Hd + c];
        float wb2 = W1[(NFd + k + 2) * Hd + c], wb3 = W1[(NFd + k + 3) * Hd + c];
        float d0 = wt0 - wb0, d1 = wt1 - wb1, d2 = wt2 - wb2, d3 = wt3 - wb3;
#pragma unroll
        for (int m = 0; m < 8; m++) {
            float4 h = *(const float4*)&sh[m][k];
            accA[m] += h.x * d0; accA[m] += h.y * d1;
            accA[m] += h.z * d2; accA[m] += h.w * d3;
            accB[m] += h.x * wb0; accB[m] += h.y * wb1;
            accB[m] += h.z * wb2; accB[m] += h.w * wb3;
        }
    }
    float bb = b1[c];
#pragma unroll
    for (int m = 0; m < 8; m++) {
        g_A[(size_t)(nb + m) * Hd + c] = accA[m] + bb;
        g_B[(size_t)(nb + m) * Hd + c] = accB[m];
    }
}

// ---------------- HMMA node GEMM: [g_A|g_B] = Hin @ [Wdiff|Wb] -----------
#define NAB_WH 0
#define NAB_WL 65536
#define NAB_PH 131072
#define NAB_PL 163840
#define NAB_TOT 196608

__global__ __launch_bounds__(512, 1) void k_gemmAB_h(const float* __restrict__ b1,
                                                     const float* __restrict__ bdec,
                                                     int fuse) {
    extern __shared__ char sm[];
    const uint32_t smb = smem_u32(sm);
    const int tid = threadIdx.x, wid = tid >> 5, lane = tid & 31;
    const int m0 = blockIdx.x * 128;

    {
        const uint4* wh = (const uint4*)g_WabH;
        const uint4* wl = (const uint4*)g_WabL;
        uint4* dh = (uint4*)(sm + NAB_WH);
        uint4* dl = (uint4*)(sm + NAB_WL);
        for (int i = tid; i < 4096; i += 512) { dh[i] = wh[i]; dl[i] = wl[i]; }
    }
#pragma unroll
    for (int i = 0; i < 4; i++) {
        int g = tid + i * 512;
        int e = g >> 4, q = g & 15;
        int row = m0 + e;
        float4 a0, a1;
        if (row < Nn) {
            if (fuse) {
                const uint4* Sr = (const uint4*)((const unsigned*)g_S + (size_t)row * 128) + q * 2;
                uint4 u0 = Sr[0], u1 = Sr[1];
                bool ok = g_deg[row] > 0;
                const float* bb = bdec + q * 8;
                a0.x = ok ? fmaxf(decf(u0.x) + bb[0], 0.f) : 0.f;
                a0.y = ok ? fmaxf(decf(u0.y) + bb[1], 0.f) : 0.f;
                a0.z = ok ? fmaxf(decf(u0.z) + bb[2], 0.f) : 0.f;
                a0.w = ok ? fmaxf(decf(u0.w) + bb[3], 0.f) : 0.f;
                a1.x = ok ? fmaxf(decf(u1.x) + bb[4], 0.f) : 0.f;
                a1.y = ok ? fmaxf(decf(u1.y) + bb[5], 0.f) : 0.f;
                a1.z = ok ? fmaxf(decf(u1.z) + bb[6], 0.f) : 0.f;
                a1.w = ok ? fmaxf(decf(u1.w) + bb[7], 0.f) : 0.f;
            } else {
                const float4* Hr = (const float4*)(g_Hf + (size_t)row * 128) + q * 2;
                a0 = Hr[0]; a1 = Hr[1];
            }
        } else {
            a0 = make_float4(0.f, 0.f, 0.f, 0.f);
            a1 = a0;
        }
        unsigned hw[4], lw[4];
        splitbf(a0.x, a0.y, hw[0], lw[0]);
        splitbf(a0.z, a0.w, hw[1], lw[1]);
        splitbf(a1.x, a1.y, hw[2], lw[2]);
        splitbf(a1.z, a1.w, hw[3], lw[3]);
        int off = e * 256 + ((q * 16) ^ ((e & 7) << 4));
        *(uint4*)(sm + NAB_PH + off) = make_uint4(hw[0], hw[1], hw[2], hw[3]);
        *(uint4*)(sm + NAB_PL + off) = make_uint4(lw[0], lw[1], lw[2], lw[3]);
    }
    __syncthreads();

    uint32_t ah[32], al[32];
    {
        int grp = lane >> 3;
        int row = 16 * (wid & 7) + (lane & 7) + (grp & 1) * 8;
        int kbb = (grp >> 1) * 16;
        int sw = (row & 7) << 4;
        uint32_t rowa = smb + NAB_PH + row * 256;
#pragma unroll
        for (int kk = 0; kk < 8; kk++) {
            uint32_t a = rowa + ((kbb + kk * 32) ^ sw);
            LDMX4(ah[kk * 4 + 0], ah[kk * 4 + 1], ah[kk * 4 + 2], ah[kk * 4 + 3], a);
            LDMX4(al[kk * 4 + 0], al[kk * 4 + 1], al[kk * 4 + 2], al[kk * 4 + 3],
                  a + (NAB_PL - NAB_PH));
        }
    }

    const int nh = wid >> 3;
    const int colbase = 128 * nh;
    const int e0 = 16 * (wid & 7) + (lane >> 2);
    const int gr0 = m0 + e0, gr1 = gr0 + 8;
    const int cl = 2 * (lane & 3);
    float* outArr = nh ? g_B : g_A;

    for (int tt = 0; tt < 16; tt++) {
        float d0 = 0.f, d1 = 0.f, d2 = 0.f, d3 = 0.f;
        int n = colbase + 8 * tt + (lane & 7);
        int nsw = (n & 7) << 4;
        uint32_t nbase = smb + NAB_WH + n * 256;
#pragma unroll
        for (int kk = 0; kk < 8; kk += 2) {
            uint32_t addr = nbase + ((kk * 32 + (lane >> 3) * 16) ^ nsw);
            uint32_t bh0, bh1, bh2, bh3, bl0, bl1, bl2, bl3;
            LDMX4(bh0, bh1, bh2, bh3, addr);
            LDMX4(bl0, bl1, bl2, bl3, addr + (NAB_WL - NAB_WH));
            const uint32_t* A0 = &ah[kk * 4];
            const uint32_t* A1 = &ah[kk * 4 + 4];
            const uint32_t* L0 = &al[kk * 4];
            const uint32_t* L1 = &al[kk * 4 + 4];
            MMA16816(d0, d1, d2, d3, A0[0], A0[1], A0[2], A0[3], bh0, bh1);
            MMA16816(d0, d1, d2, d3, A1[0], A1[1], A1[2], A1[3], bh2, bh3);
            MMA16816(d0, d1, d2, d3, A0[0], A0[1], A0[2], A0[3], bl0, bl1);
            MMA16816(d0, d1, d2, d3, A1[0], A1[1], A1[2], A1[3], bl2, bl3);
            MMA16816(d0, d1, d2, d3, L0[0], L0[1], L0[2], L0[3], bh0, bh1);
            MMA16816(d0, d1, d2, d3, L1[0], L1[1], L1[2], L1[3], bh2, bh3);
        }
        int c = 8 * tt + cl;
        float bb0 = 0.f, bb1 = 0.f;
        if (nh == 0) { bb0 = b1[c]; bb1 = b1[c + 1]; }
        if (gr0 < Nn)
            *(float2*)(outArr + (size_t)gr0 * 128 + c) = make_float2(d0 + bb0, d1 + bb1);
        if (gr1 < Nn)
            *(float2*)(outArr + (size_t)gr1 * 128 + c) = make_float2(d2 + bb0, d3 + bb1);
    }
}

// ---------------- HMMA node GEMM: g_Hf = f((g_S/deg)@W2 + b2) ------------
// single-buffered P (hi then lo) -> 98.8KB SMEM -> 2 CTA/SM
#define NS_WH 0
#define NS_WL 32768
#define NS_P  65536
#define NS_SINV 98304
#define NS_WF   98816
#define NS_TOT  (98816 + 2048)

__global__ __launch_bounds__(256, 2) void k_gemmS_h(const float* __restrict__ b2,
                                                    int doRelu, int doFc,
                                                    const float* __restrict__ Wf,
                                                    const float* __restrict__ bfv,
                                                    float* __restrict__ out) {
    extern __shared__ char sm[];
    const uint32_t smb = smem_u32(sm);
    const int tid = threadIdx.x, wid = tid >> 5, lane = tid & 31;
    const int m0 = blockIdx.x * 128;
    float* sinv = (float*)(sm + NS_SINV);
    float4* sWf = (float4*)(sm + NS_WF);

    {
        const uint4* wh = (const uint4*)g_WsH;
        const uint4* wl = (const uint4*)g_WsL;
        uint4* dh = (uint4*)(sm + NS_WH);
        uint4* dl = (uint4*)(sm + NS_WL);
        for (int i = tid; i < 2048; i += 256) { dh[i] = wh[i]; dl[i] = wl[i]; }
    }
    if (tid < 128) {
        int row = m0 + tid;
        int d = (row < Nn) ? g_deg[row] : 0;
        sinv[tid] = (d > 0) ? 1.0f / (float)d : 0.f;
        if (doFc) sWf[tid] = ((const float4*)Wf)[tid];
    }
    __syncthreads();

    // ---- build pass A: P <- hi words ----
#pragma unroll
    for (int i = 0; i < 8; i++) {
        int g = tid + i * 256;
        int e = g >> 4, q = g & 15;
        int row = m0 + e;
        float s = sinv[e];
        float4 a0, a1;
        if (row < Nn) {
            const float4* Sr = (const float4*)(g_S + (size_t)row * 128) + q * 2;
            a0 = Sr[0]; a1 = Sr[1];
            a0.x *= s; a0.y *= s; a0.z *= s; a0.w *= s;
            a1.x *= s; a1.y *= s; a1.z *= s; a1.w *= s;
        } else {
            a0 = make_float4(0.f, 0.f, 0.f, 0.f);
            a1 = a0;
        }
        unsigned hw[4];
        hw[0] = hibf(a0.x, a0.y);
        hw[1] = hibf(a0.z, a0.w);
        hw[2] = hibf(a1.x, a1.y);
        hw[3] = hibf(a1.z, a1.w);
        int off = e * 256 + ((q * 16) ^ ((e & 7) << 4));
        *(uint4*)(sm + NS_P + off) = make_uint4(hw[0], hw[1], hw[2], hw[3]);
    }
    __syncthreads();

    uint32_t ah[32], al[32];
    const int grp = lane >> 3;
    const int arow = 16 * wid + (lane & 7) + (grp & 1) * 8;
    const int kbb = (grp >> 1) * 16;
    const int asw = (arow & 7) << 4;
    {
        uint32_t rowa = smb + NS_P + arow * 256;
#pragma unroll
        for (int kk = 0; kk < 8; kk++) {
            uint32_t a = rowa + ((kbb + kk * 32) ^ asw);
            LDMX4(ah[kk * 4 + 0], ah[kk * 4 + 1], ah[kk * 4 + 2], ah[kk * 4 + 3], a);
        }
    }
    __syncthreads();   // all warps done reading P-hi

    // ---- build pass B: P <- lo words (recompute split) ----
#pragma unroll
    for (int i = 0; i < 8; i++) {
        int g = tid + i * 256;
        int e = g >> 4, q = g & 15;
        int row = m0 + e;
        float s = sinv[e];
        float4 a0, a1;
        if (row < Nn) {
            const float4* Sr = (const float4*)(g_S + (size_t)row * 128) + q * 2;
            a0 = Sr[0]; a1 = Sr[1];
            a0.x *= s; a0.y *= s; a0.z *= s; a0.w *= s;
            a1.x *= s; a1.y *= s; a1.z *= s; a1.w *= s;
        } else {
            a0 = make_float4(0.f, 0.f, 0.f, 0.f);
            a1 = a0;
        }
        unsigned hw, lw[4];
        splitbf(a0.x, a0.y, hw, lw[0]);
        splitbf(a0.z, a0.w, hw, lw[1]);
        splitbf(a1.x, a1.y, hw, lw[2]);
        splitbf(a1.z, a1.w, hw, lw[3]);
        int off = e * 256 + ((q * 16) ^ ((e & 7) << 4));
        *(uint4*)(sm + NS_P + off) = make_uint4(lw[0], lw[1], lw[2], lw[3]);
    }
    __syncthreads();

    {
        uint32_t rowa = smb + NS_P + arow * 256;
#pragma unroll
        for (int kk = 0; kk < 8; kk++) {
            uint32_t a = rowa + ((kbb + kk * 32) ^ asw);
            LDMX4(al[kk * 4 + 0], al[kk * 4 + 1], al[kk * 4 + 2], al[kk * 4 + 3], a);
        }
    }

    const int e0 = 16 * wid + (lane >> 2);
    const int gr0 = m0 + e0, gr1 = gr0 + 8;
    const int cl = 2 * (lane & 3);
    const bool z0 = sinv[e0] > 0.f, z1 = sinv[e0 + 8] > 0.f;

    float4 p0 = make_float4(0.f, 0.f, 0.f, 0.f);
    float4 p1 = make_float4(0.f, 0.f, 0.f, 0.f);

    for (int tt = 0; tt < 16; tt++) {
        float d0 = 0.f, d1 = 0.f, d2 = 0.f, d3 = 0.f;
        int n = 8 * tt + (lane & 7);
        int nsw = (n & 7) << 4;
        uint32_t nbase = smb + NS_WH + n * 256;
#pragma unroll
        for (int kk = 0; kk < 8; kk += 2) {
            uint32_t addr = nbase + ((kk * 32 + (lane >> 3) * 16) ^ nsw);
            uint32_t bh0, bh1, bh2, bh3, bl0, bl1, bl2, bl3;
            LDMX4(bh0, bh1, bh2, bh3, addr);
            LDMX4(bl0, bl1, bl2, bl3, addr + (NS_WL - NS_WH));
            const uint32_t* A0 = &ah[kk * 4];
            const uint32_t* A1 = &ah[kk * 4 + 4];
            const uint32_t* L0 = &al[kk * 4];
            const uint32_t* L1 = &al[kk * 4 + 4];
            MMA16816(d0, d1, d2, d3, A0[0], A0[1], A0[2], A0[3], bh0, bh1);
            MMA16816(d0, d1, d2, d3, A1[0], A1[1], A1[2], A1[3], bh2, bh3);
            MMA16816(d0, d1, d2, d3, A0[0], A0[1], A0[2], A0[3], bl0, bl1);
            MMA16816(d0, d1, d2, d3, A1[0], A1[1], A1[2], A1[3], bl2, bl3);
            MMA16816(d0, d1, d2, d3, L0[0], L0[1], L0[2], L0[3], bh0, bh1);
            MMA16816(d0, d1, d2, d3, L1[0], L1[1], L1[2], L1[3], bh2, bh3);
        }
        int c = 8 * tt + cl;
        float bb0 = b2[c], bb1 = b2[c + 1];
        float v0 = z0 ? (d0 + bb0) : 0.f;
        float v1 = z0 ? (d1 + bb1) : 0.f;
        float v2 = z1 ? (d2 + bb0) : 0.f;
        float v3 = z1 ? (d3 + bb1) : 0.f;
        if (doRelu) {
            v0 = fmaxf(v0, 0.f); v1 = fmaxf(v1, 0.f);
            v2 = fmaxf(v2, 0.f); v3 = fmaxf(v3, 0.f);
        }
        if (doFc) {
            float4 wc = sWf[c], wc1 = sWf[c + 1];
            p0.x += v0 * wc.x + v1 * wc1.x;
            p0.y += v0 * wc.y + v1 * wc1.y;
            p0.z += v0 * wc.z + v1 * wc1.z;
            p0.w += v0 * wc.w + v1 * wc1.w;
            p1.x += v2 * wc.x + v3 * wc1.x;
            p1.y += v2 * wc.y + v3 * wc1.y;
            p1.z += v2 * wc.z + v3 * wc1.z;
            p1.w += v2 * wc.w + v3 * wc1.w;
        } else {
            if (gr0 < Nn) *(float2*)(g_Hf + (size_t)gr0 * 128 + c) = make_float2(v0, v1);
            if (gr1 < Nn) *(float2*)(g_Hf + (size_t)gr1 * 128 + c) = make_float2(v2, v3);
        }
    }

    if (doFc) {
#pragma unroll
        for (int off = 1; off <= 2; off <<= 1) {
            p0.x += __shfl_xor_sync(0xffffffffu, p0.x, off);
            p0.y += __shfl_xor_sync(0xffffffffu, p0.y, off);
            p0.z += __shfl_xor_sync(0xffffffffu, p0.z, off);
            p0.w += __shfl_xor_sync(0xffffffffu, p0.w, off);
            p1.x += __shfl_xor_sync(0xffffffffu, p1.x, off);
            p1.y += __shfl_xor_sync(0xffffffffu, p1.y, off);
            p1.z += __shfl_xor_sync(0xffffffffu, p1.z, off);
            p1.w += __shfl_xor_sync(0xffffffffu, p1.w, off);
        }
        if ((lane & 3) == 0) {
            float4 bf4 = make_float4(bfv[0], bfv[1], bfv[2], bfv[3]);
            if (gr0 < Nn)
                ((float4*)out)[gr0] = make_float4(p0.x + bf4.x, p0.y + bf4.y,
                                                  p0.z + bf4.z, p0.w + bf4.w);
            if (gr1 < Nn)
                ((float4*)out)[gr1] = make_float4(p1.x + bf4.x, p1.y + bf4.y,
                                                  p1.z + bf4.z, p1.w + bf4.w);
        }
    }
}

// ---------------- layer0 edge GEMM (R13 known-good) ----------------------
#define DSTR 68
#define E_W2H 0
#define E_W2L 32768
#define E_P   65536
#define E_PL  (E_P + 16384)
#define E_TOT (E_P + 128 * DSTR * 4)    // 100352

__global__ __launch_bounds__(256, 2) void k_edge_hmma() {
    extern __shared__ char sm[];
    const uint32_t smb = smem_u32(sm);
    const int tid = threadIdx.x, wid = tid >> 5, lane = tid & 31;
    const int mslot = wid & 3;
    const int nh = wid >> 2;

    {
        const uint4* wh = (const uint4*)g_W2h_img;
        const uint4* wl = (const uint4*)g_W2l_img;
        uint4* dh = (uint4*)(sm + E_W2H);
        uint4* dl = (uint4*)(sm + E_W2L);
        for (int i = tid; i < 2048; i += 256) { dh[i] = wh[i]; dl[i] = wl[i]; }
    }
    __syncthreads();

    unsigned* encOut = (unsigned*)g_S;
    float* Dst = (float*)(sm + E_P);

    for (int t = blockIdx.x; t < NT64; t += gridDim.x) {
        const int ebase = t * ET;
#pragma unroll
        for (int i = 0; i < 4; i++) {
            int g = tid + i * 256;
            int e = g >> 4, q = g & 15;
            int dst = g_edst[ebase + e];
            int src = g_colidx[ebase + e];
            const float4* Ar = (const float4*)(g_A + (size_t)dst * 128) + q * 2;
            const float4* Br = (const float4*)(g_B + (size_t)src * 128) + q * 2;
            float4 a0 = Ar[0], a1 = Ar[1];
            float4 b0 = Br[0], b1 = Br[1];
            float v[8];
            v[0] = fmaxf(a0.x + b0.x, 0.f); v[1] = fmaxf(a0.y + b0.y, 0.f);
            v[2] = fmaxf(a0.z + b0.z, 0.f); v[3] = fmaxf(a0.w + b0.w, 0.f);
            v[4] = fmaxf(a1.x + b1.x, 0.f); v[5] = fmaxf(a1.y + b1.y, 0.f);
            v[6] = fmaxf(a1.z + b1.z, 0.f); v[7] = fmaxf(a1.w + b1.w, 0.f);
            unsigned hw[4], lw[4];
            splitbf(v[0], v[1], hw[0], lw[0]);
            splitbf(v[2], v[3], hw[1], lw[1]);
            splitbf(v[4], v[5], hw[2], lw[2]);
            splitbf(v[6], v[7], hw[3], lw[3]);
            int off = e * 256 + ((q * 16) ^ ((e & 7) << 4));
            *(uint4*)(sm + E_P + off) = make_uint4(hw[0], hw[1], hw[2], hw[3]);
            *(uint4*)(sm + E_PL + off) = make_uint4(lw[0], lw[1], lw[2], lw[3]);
        }
        __syncthreads();

        uint32_t ah[32], al[32];
        {
            int grp = lane >> 3;
            int row = 16 * mslot + (lane & 7) + (grp & 1) * 8;
            int kbb = (grp >> 1) * 16;
            int sw = (row & 7) << 4;
            uint32_t rowa = smb + E_P + row * 256;
#pragma unroll
            for (int kk = 0; kk < 8; kk++) {
                uint32_t a = rowa + ((kbb + kk * 32) ^ sw);
                LDMX4(ah[kk * 4 + 0], ah[kk * 4 + 1], ah[kk * 4 + 2], ah[kk * 4 + 3], a);
                LDMX4(al[kk * 4 + 0], al[kk * 4 + 1], al[kk * 4 + 2], al[kk * 4 + 3],
                      a + 16384);
            }
        }
        __syncthreads();

        {
            const int e0 = 16 * mslot + (lane >> 2), e1 = e0 + 8;
            const int cl = 2 * (lane & 3);
#pragma unroll
            for (int tp = 0; tp < 4; tp++) {
                float da0 = 0.f, da1 = 0.f, da2 = 0.f, da3 = 0.f;
                float db0 = 0.f, db1 = 0.f, db2 = 0.f, db3 = 0.f;
                int na = nh * 64 + 16 * tp + (lane & 7);
                int nb = na + 8;
                int nswa = (na & 7) << 4, nswb = (nb & 7) << 4;
                uint32_t nbasea = smb + E_W2H + na * 256;
                uint32_t nbaseb = smb + E_W2H + nb * 256;
#pragma unroll
                for (int kk = 0; kk < 8; kk += 2) {
                    uint32_t ka = ((kk * 32 + (lane >> 3) * 16));
                    uint32_t addra = nbasea + (ka ^ nswa);
                    uint32_t addrb = nbaseb + (ka ^ nswb);
                    uint32_t ah0, ah1, ah2, ah3, al0, al1, al2, al3;
                    uint32_t bh0, bh1, bh2, bh3, bl0, bl1, bl2, bl3;
                    LDMX4(ah0, ah1, ah2, ah3, addra);
                    LDMX4(al0, al1, al2, al3, addra + 32768);
                    LDMX4(bh0, bh1, bh2, bh3, addrb);
                    LDMX4(bl0, bl1, bl2, bl3, addrb + 32768);
                    const uint32_t* A0 = &ah[kk * 4];
                    const uint32_t* A1 = &ah[kk * 4 + 4];
                    const uint32_t* L0 = &al[kk * 4];
                    const uint32_t* L1 = &al[kk * 4 + 4];
                    MMA16816(da0, da1, da2, da3, A0[0], A0[1], A0[2], A0[3], ah0, ah1);
                    MMA16816(db0, db1, db2, db3, A0[0], A0[1], A0[2], A0[3], bh0, bh1);
                    MMA16816(da0, da1, da2, da3, A1[0], A1[1], A1[2], A1[3], ah2, ah3);
                    MMA16816(db0, db1, db2, db3, A1[0], A1[1], A1[2], A1[3], bh2, bh3);
                    MMA16816(da0, da1, da2, da3, A0[0], A0[1], A0[2], A0[3], al0, al1);
                    MMA16816(db0, db1, db2, db3, A0[0], A0[1], A0[2], A0[3], bl0, bl1);
                    MMA16816(da0, da1, da2, da3, A1[0], A1[1], A1[2], A1[3], al2, al3);
                    MMA16816(db0, db1, db2, db3, A1[0], A1[1], A1[2], A1[3], bl2, bl3);
                    MMA16816(da0, da1, da2, da3, L0[0], L0[1], L0[2], L0[3], ah0, ah1);
                    MMA16816(db0, db1, db2, db3, L0[0], L0[1], L0[2], L0[3], bh0, bh1);
                    MMA16816(da0, da1, da2, da3, L1[0], L1[1], L1[2], L1[3], ah2, ah3);
                    MMA16816(db0, db1, db2, db3, L1[0], L1[1], L1[2], L1[3], bh2, bh3);
                }
                int ca = nh * 64 + 16 * tp + cl;
                int cb = ca + 8;
                Dst[ca * DSTR + e0] = da0;
                Dst[(ca + 1) * DSTR + e0] = da1;
                Dst[ca * DSTR + e1] = da2;
                Dst[(ca + 1) * DSTR + e1] = da3;
                Dst[cb * DSTR + e0] = db0;
                Dst[(cb + 1) * DSTR + e0] = db1;
                Dst[cb * DSTR + e1] = db2;
                Dst[(cb + 1) * DSTR + e1] = db3;
            }
        }
        __syncthreads();

        {
            int e = (wid & 1) * 32 + lane;
            int dstv = g_edst[ebase + e];
            unsigned mm = __match_any_sync(0xffffffffu, dstv);
            bool leader = ((int)(__ffs(mm) - 1) == lane);
            int cbase = (wid >> 1) * 32;
            unsigned* outp = encOut + (size_t)dstv * 128 + cbase;
#pragma unroll 8
            for (int c = 0; c < 32; c++) {
                float v = Dst[(cbase + c) * DSTR + e];
                unsigned red = __reduce_max_sync(mm, encf(v));
                if (leader) atomicMax(outp + c, red);
            }
        }
        __syncthreads();
    }
}

// ---------------- mean layers: S_i = sum_e relu(A_i + B_src), MLP=8 ------
__global__ __launch_bounds__(256) void k_edge_sum() {
    int gw = (blockIdx.x * 256 + threadIdx.x) >> 5;
    int lane = threadIdx.x & 31;
    if (gw >= Nn) return;
    const float4 a = *(const float4*)&g_A[(size_t)gw * Hd + lane * 4];
    float4 acc = make_float4(0.f, 0.f, 0.f, 0.f);
    int p = g_rowptr[gw], p1 = g_rowptr[gw + 1];
    for (; p + 8 <= p1; p += 8) {
        int j0 = g_colidx[p],     j1 = g_colidx[p + 1];
        int j2 = g_colidx[p + 2], j3 = g_colidx[p + 3];
        int j4 = g_colidx[p + 4], j5 = g_colidx[p + 5];
        int j6 = g_colidx[p + 6], j7 = g_colidx[p + 7];
        float4 b0 = *(const float4*)&g_B[(size_t)j0 * Hd + lane * 4];
        float4 b1 = *(const float4*)&g_B[(size_t)j1 * Hd + lane * 4];
        float4 b2 = *(const float4*)&g_B[(size_t)j2 * Hd + lane * 4];
        float4 b3 = *(const float4*)&g_B[(size_t)j3 * Hd + lane * 4];
        float4 b4 = *(const float4*)&g_B[(size_t)j4 * Hd + lane * 4];
        float4 b5 = *(const float4*)&g_B[(size_t)j5 * Hd + lane * 4];
        float4 b6 = *(const float4*)&g_B[(size_t)j6 * Hd + lane * 4];
        float4 b7 = *(const float4*)&g_B[(size_t)j7 * Hd + lane * 4];
        acc.x += fmaxf(a.x + b0.x, 0.f) + fmaxf(a.x + b1.x, 0.f)
               + fmaxf(a.x + b2.x, 0.f) + fmaxf(a.x + b3.x, 0.f)
               + fmaxf(a.x + b4.x, 0.f) + fmaxf(a.x + b5.x, 0.f)
               + fmaxf(a.x + b6.x, 0.f) + fmaxf(a.x + b7.x, 0.f);
        acc.y += fmaxf(a.y + b0.y, 0.f) + fmaxf(a.y + b1.y, 0.f)
               + fmaxf(a.y + b2.y, 0.f) + fmaxf(a.y + b3.y, 0.f)
               + fmaxf(a.y + b4.y, 0.f) + fmaxf(a.y + b5.y, 0.f)
               + fmaxf(a.y + b6.y, 0.f) + fmaxf(a.y + b7.y, 0.f);
        acc.z += fmaxf(a.z + b0.z, 0.f) + fmaxf(a.z + b1.z, 0.f)
               + fmaxf(a.z + b2.z, 0.f) + fmaxf(a.z + b3.z, 0.f)
               + fmaxf(a.z + b4.z, 0.f) + fmaxf(a.z + b5.z, 0.f)
               + fmaxf(a.z + b6.z, 0.f) + fmaxf(a.z + b7.z, 0.f);
        acc.w += fmaxf(a.w + b0.w, 0.f) + fmaxf(a.w + b1.w, 0.f)
               + fmaxf(a.w + b2.w, 0.f) + fmaxf(a.w + b3.w, 0.f)
               + fmaxf(a.w + b4.w, 0.f) + fmaxf(a.w + b5.w, 0.f)
               + fmaxf(a.w + b6.w, 0.f) + fmaxf(a.w + b7.w, 0.f);
    }
    for (; p + 4 <= p1; p += 4) {
        int j0 = g_colidx[p], j1 = g_colidx[p + 1];
        int j2 = g_colidx[p + 2], j3 = g_colidx[p + 3];
        float4 b0 = *(const float4*)&g_B[(size_t)j0 * Hd + lane * 4];
        float4 b1 = *(const float4*)&g_B[(size_t)j1 * Hd + lane * 4];
        float4 b2 = *(const float4*)&g_B[(size_t)j2 * Hd + lane * 4];
        float4 b3 = *(const float4*)&g_B[(size_t)j3 * Hd + lane * 4];
        acc.x += fmaxf(a.x + b0.x, 0.f) + fmaxf(a.x + b1.x, 0.f)
               + fmaxf(a.x + b2.x, 0.f) + fmaxf(a.x + b3.x, 0.f);
        acc.y += fmaxf(a.y + b0.y, 0.f) + fmaxf(a.y + b1.y, 0.f)
               + fmaxf(a.y + b2.y, 0.f) + fmaxf(a.y + b3.y, 0.f);
        acc.z += fmaxf(a.z + b0.z, 0.f) + fmaxf(a.z + b1.z, 0.f)
               + fmaxf(a.z + b2.z, 0.f) + fmaxf(a.z + b3.z, 0.f);
        acc.w += fmaxf(a.w + b0.w, 0.f) + fmaxf(a.w + b1.w, 0.f)
               + fmaxf(a.w + b2.w, 0.f) + fmaxf(a.w + b3.w, 0.f);
    }
    for (; p < p1; p++) {
        int j = g_colidx[p];
        float4 b = *(const float4*)&g_B[(size_t)j * Hd + lane * 4];
        acc.x += fmaxf(a.x + b.x, 0.f);
        acc.y += fmaxf(a.y + b.y, 0.f);
        acc.z += fmaxf(a.z + b.z, 0.f);
        acc.w += fmaxf(a.w + b.w, 0.f);
    }
    *(float4*)&g_S[(size_t)gw * Hd + lane * 4] = acc;
}

// ---------------- launch ----------------
extern "C" void kernel_launch(void* const* d_in, const int* in_sizes, int n_in,
                              void* d_out, int out_size) {
    const float* x   = (const float*)d_in[0];
    const void*  ei  = (const void*)d_in[2];
    const float* W01 = (const float*)d_in[3];
    const float* b01 = (const float*)d_in[4];
    const float* W02 = (const float*)d_in[5];
    const float* b02 = (const float*)d_in[6];
    const float* W11 = (const float*)d_in[7];
    const float* b11 = (const float*)d_in[8];
    const float* W12 = (const float*)d_in[9];
    const float* b12 = (const float*)d_in[10];
    const float* W21 = (const float*)d_in[11];
    const float* b21 = (const float*)d_in[12];
    const float* W22 = (const float*)d_in[13];
    const float* b22 = (const float*)d_in[14];
    const float* Wf  = (const float*)d_in[15];
    const float* bf  = (const float*)d_in[16];
    float* out = (float*)d_out;

    cudaFuncSetAttribute(k_edge_hmma, cudaFuncAttributeMaxDynamicSharedMemorySize, E_TOT);
    cudaFuncSetAttribute(k_gemmAB_h, cudaFuncAttributeMaxDynamicSharedMemorySize, NAB_TOT);
    cudaFuncSetAttribute(k_gemmS_h, cudaFuncAttributeMaxDynamicSharedMemorySize, NS_TOT);

    const int NB = (Nn + 255) / 256;

    // CSR build + zeroing
    k_zero_all<<<(Nn * Hd / 4 + 255) / 256, 256>>>(ei);
    k_deg<<<Ee / 256, 256>>>(ei);
    k_scan1<<<NB, 256>>>();
    k_scan2<<<1, 256>>>(NB);
    k_scan3<<<NB, 256>>>();
    k_scatter<<<Ee / 256, 256>>>(ei);

    // layer 0 (max) on HMMA
    k_prepW2<<<64, 256>>>(W02);
    k_gemmAB16<<<Nn / 8, 128>>>(x, W01, b01);
    k_edge_hmma<<<296, 256, E_TOT>>>();

    // layer 1 (mean) + relu — layer0 decode fused into gemmAB_h
    k_prepNode<<<192, 256>>>(W11, W12);
    k_gemmAB_h<<<MTILES, 512, NAB_TOT>>>(b11, b02, 1);
    k_edge_sum<<<Nn / 8, 256>>>();
    k_gemmS_h<<<MTILES, 256, NS_TOT>>>(b12, 1, 0, nullptr, nullptr, nullptr);

    // layer 2 (mean), no relu; final FC fused into gemmS_h
    k_prepNode<<<192, 256>>>(W21, W22);
    k_gemmAB_h<<<MTILES, 512, NAB_TOT>>>(b21, nullptr, 0);
    k_edge_sum<<<Nn / 8, 256>>>();
    k_gemmS_h<<<MTILES, 256, NS_TOT>>>(b22, 0, 1, Wf, bf, out);
}